// round 12
// baseline (speedup 1.0000x reference)
#include <cuda_runtime.h>
#include <cuda_fp16.h>
#include <mma.h>
#include <cstdint>
using namespace nvcuda;

// Problem dims (fixed)
#define BB   1024
#define TT   128
#define DD   128
#define HH   8
#define HDIM 16
#define FFD  512
#define NL   2
#define MM   (BB*TT)          // 131072 tokens

// fp16 scratch
__device__ __half g_wqkv[(size_t)NL * 3 * DD * DD];
__device__ __half g_wout[(size_t)NL * DD * DD];
__device__ __half g_wff1[(size_t)NL * FFD * DD];
__device__ __half g_wff2[(size_t)NL * DD * FFD];
__device__ __half g_xh  [(size_t)MM * DD];
__device__ __half g_qkvh[(size_t)MM * 3 * DD];
__device__ __half g_attnh[(size_t)MM * DD];

// ---------------------------------------------------------------------------
#define N_XH4 (MM * DD / 4)
#define N_WQ4 (NL * 3 * DD * DD / 4)
#define N_WO4 (NL * DD * DD / 4)
#define N_W14 (NL * FFD * DD / 4)
#define N_W24 (NL * DD * FFD / 4)
#define N_CVT (N_XH4 + N_WQ4 + N_WO4 + N_W14 + N_W24)

__global__ void cvt_all(const float* __restrict__ x,
                        const float* __restrict__ wq,
                        const float* __restrict__ wo,
                        const float* __restrict__ w1,
                        const float* __restrict__ w2)
{
    long i = (long)blockIdx.x * blockDim.x + threadIdx.x;
    if (i >= N_CVT) return;
    const float* src;
    __half* dst;
    long off = i;
    if (off < N_XH4)                      { src = x;  dst = g_xh;   }
    else if ((off -= N_XH4) < N_WQ4)      { src = wq; dst = g_wqkv; }
    else if ((off -= N_WQ4) < N_WO4)      { src = wo; dst = g_wout; }
    else if ((off -= N_WO4) < N_W14)      { src = w1; dst = g_wff1; }
    else  { off -= N_W14;                   src = w2; dst = g_wff2; }
    float4 v = ((const float4*)src)[off];
    __half2 h0 = __floats2half2_rn(v.x, v.y);
    __half2 h1 = __floats2half2_rn(v.z, v.w);
    uint2 u;
    u.x = *reinterpret_cast<uint32_t*>(&h0);
    u.y = *reinterpret_cast<uint32_t*>(&h1);
    ((uint2*)dst)[off] = u;
}

__device__ __forceinline__ uint32_t smem_u32(const void* p) {
    uint32_t a;
    asm("{ .reg .u64 t; cvta.to.shared.u64 t, %1; cvt.u32.u64 %0, t; }"
        : "=r"(a) : "l"(p));
    return a;
}
__device__ __forceinline__ void cp16(uint32_t dst, const void* src) {
    asm volatile("cp.async.ca.shared.global [%0], [%1], 16;" :: "r"(dst), "l"(src));
}
__device__ __forceinline__ float fast_exp_s6(float x) {
    x = fmaxf(x, -80.f);
    float t  = x * 1.4426950408889634f;
    float fn = t + 12582912.f;
    int   ni = __float_as_int(fn) - 0x4B400000;
    float r  = t - (fn - 12582912.f);
    float p  = 0.00133336f;
    p = fmaf(p, r, 0.00961813f);
    p = fmaf(p, r, 0.05550411f);
    p = fmaf(p, r, 0.24022651f);
    p = fmaf(p, r, 0.69314718f);
    p = fmaf(p, r, 1.0f);
    return p * __int_as_float((ni + 121) << 23);   // * 2^(n-6)
}

// ---------------------------------------------------------------------------
// gemm_h (R9 proven): qkv (mode 0) + out-proj + LN1 (mode 2).
// Tile 128x128, BK=32, 4-stage cp.async, 256 threads, 8 warps x 64x32, 2 CTA/SM.
// ---------------------------------------------------------------------------
#define BK   32
#define ALD  40
#define STG_B 20480
#define NS   4
#define CLD  132
#define SMEM_DYN (NS*STG_B)

__global__ __launch_bounds__(256, 2) void gemm_h(
    const __half* __restrict__ A, const __half* __restrict__ W,
    const float* __restrict__ bias,
    __half* __restrict__ Ch,
    float* __restrict__ X, __half* __restrict__ Xh,
    const float* __restrict__ gamma, const float* __restrict__ beta,
    int N, int K, int mode)
{
    extern __shared__ __align__(16) char smem[];
    const uint32_t sbase = smem_u32(smem);
    const int tid  = threadIdx.x;
    const int wid  = tid >> 5;
    const int lane = tid & 31;
    const int wm   = wid & 1;
    const int wn   = wid >> 1;
    const size_t bm = (size_t)blockIdx.y * 128;
    const size_t bn = (size_t)blockIdx.x * 128;
    const int NT = K / BK;

    const int rA0 = tid >> 2, cA0 = tid & 3;
    const int rA1 = (tid + 256) >> 2, cA1 = (tid + 256) & 3;

    wmma::fragment<wmma::accumulator, 16, 16, 16, float> acc[4][2];
#pragma unroll
    for (int i = 0; i < 4; i++)
#pragma unroll
        for (int j = 0; j < 2; j++) wmma::fill_fragment(acc[i][j], 0.f);

#pragma unroll
    for (int t = 0; t < NS - 1; t++) {
        if (t < NT) {
            const int kk = t * BK;
            const uint32_t sb = sbase + (t % NS) * STG_B;
            cp16(sb + (rA0 * ALD + cA0 * 8) * 2, A + (bm + rA0) * K + kk + cA0 * 8);
            cp16(sb + (rA1 * ALD + cA1 * 8) * 2, A + (bm + rA1) * K + kk + cA1 * 8);
            cp16(sb + 10240 + (rA0 * ALD + cA0 * 8) * 2, W + (bn + rA0) * K + kk + cA0 * 8);
            cp16(sb + 10240 + (rA1 * ALD + cA1 * 8) * 2, W + (bn + rA1) * K + kk + cA1 * 8);
        }
        asm volatile("cp.async.commit_group;");
    }

    for (int t = 0; t < NT; t++) {
        asm volatile("cp.async.wait_group %0;" :: "n"(NS - 2));
        __syncthreads();
        {
            const __half* As = (const __half*)(smem + (t % NS) * STG_B);
            const __half* Ws = As + 5120;
#pragma unroll
            for (int ks = 0; ks < 2; ks++) {
                wmma::fragment<wmma::matrix_a, 16, 16, 16, __half, wmma::row_major> af[4];
                wmma::fragment<wmma::matrix_b, 16, 16, 16, __half, wmma::col_major> bf[2];
#pragma unroll
                for (int i = 0; i < 4; i++)
                    wmma::load_matrix_sync(af[i], As + (wm * 64 + i * 16) * ALD + ks * 16, ALD);
#pragma unroll
                for (int j = 0; j < 2; j++)
                    wmma::load_matrix_sync(bf[j], Ws + (wn * 32 + j * 16) * ALD + ks * 16, ALD);
#pragma unroll
                for (int i = 0; i < 4; i++)
#pragma unroll
                    for (int j = 0; j < 2; j++)
                        wmma::mma_sync(acc[i][j], af[i], bf[j], acc[i][j]);
            }
        }
        __syncthreads();
        {
            const int tn = t + NS - 1;
            if (tn < NT) {
                const int kk = tn * BK;
                const uint32_t sb = sbase + (tn % NS) * STG_B;
                cp16(sb + (rA0 * ALD + cA0 * 8) * 2, A + (bm + rA0) * K + kk + cA0 * 8);
                cp16(sb + (rA1 * ALD + cA1 * 8) * 2, A + (bm + rA1) * K + kk + cA1 * 8);
                cp16(sb + 10240 + (rA0 * ALD + cA0 * 8) * 2, W + (bn + rA0) * K + kk + cA0 * 8);
                cp16(sb + 10240 + (rA1 * ALD + cA1 * 8) * 2, W + (bn + rA1) * K + kk + cA1 * 8);
            }
            asm volatile("cp.async.commit_group;");
        }
    }

    float* smf = (float*)smem;
#pragma unroll
    for (int i = 0; i < 4; i++)
#pragma unroll
        for (int j = 0; j < 2; j++)
            wmma::store_matrix_sync(smf + (wm * 64 + i * 16) * CLD + wn * 32 + j * 16,
                                    acc[i][j], CLD, wmma::mem_row_major);
    __syncthreads();

    if (mode == 2) {
        float4 gv = *(const float4*)(gamma + lane * 4);
        float4 bv = *(const float4*)(beta  + lane * 4);
        float4 bz = *(const float4*)(bias  + lane * 4);
#pragma unroll
        for (int i = 0; i < 16; i++) {
            const int row = wid * 16 + i;
            float4 v = *(float4*)(smf + row * CLD + lane * 4);
            const size_t off = (bm + row) * DD + lane * 4;
            float4 xv = *(const float4*)(X + off);
            float4 tv;
            tv.x = v.x + bz.x + xv.x; tv.y = v.y + bz.y + xv.y;
            tv.z = v.z + bz.z + xv.z; tv.w = v.w + bz.w + xv.w;
            float s  = tv.x + tv.y + tv.z + tv.w;
            float s2 = tv.x*tv.x + tv.y*tv.y + tv.z*tv.z + tv.w*tv.w;
#pragma unroll
            for (int o = 16; o > 0; o >>= 1) {
                s  += __shfl_xor_sync(0xffffffffu, s,  o);
                s2 += __shfl_xor_sync(0xffffffffu, s2, o);
            }
            float mean = s * (1.f / DD);
            float var  = s2 * (1.f / DD) - mean * mean;
            float rstd = rsqrtf(var + 1e-5f);
            float4 y;
            y.x = (tv.x - mean) * rstd * gv.x + bv.x;
            y.y = (tv.y - mean) * rstd * gv.y + bv.y;
            y.z = (tv.z - mean) * rstd * gv.z + bv.z;
            y.w = (tv.w - mean) * rstd * gv.w + bv.w;
            *(float4*)(X + off) = y;
            __half2 h0 = __floats2half2_rn(y.x, y.y);
            __half2 h1 = __floats2half2_rn(y.z, y.w);
            uint2 u;
            u.x = *reinterpret_cast<uint32_t*>(&h0);
            u.y = *reinterpret_cast<uint32_t*>(&h1);
            *(uint2*)(Xh + off) = u;
        }
    } else {
#pragma unroll
        for (int i = 0; i < 16; i++) {
            int idx = i * 256 + tid;
            int row = idx >> 5;
            int cc  = (idx & 31) * 4;
            float4 v  = *(float4*)(smf + row * CLD + cc);
            float4 bz = *(const float4*)(bias + bn + cc);
            v.x += bz.x; v.y += bz.y; v.z += bz.z; v.w += bz.w;
            __half2 h0 = __floats2half2_rn(v.x, v.y);
            __half2 h1 = __floats2half2_rn(v.z, v.w);
            uint2 u;
            u.x = *reinterpret_cast<uint32_t*>(&h0);
            u.y = *reinterpret_cast<uint32_t*>(&h1);
            *(uint2*)(Ch + (bm + row) * N + bn + cc) = u;
        }
    }
}

// ---------------------------------------------------------------------------
// attn_tc (R9 proven): one block per (b,h), 256 threads / 8 warps, 2 CTA/SM.
// ---------------------------------------------------------------------------
#define QLD 24
#define SLD 68
#define PLD 136
#define OLD 20
#define ATT_SMEM 89088

__global__ __launch_bounds__(256, 2) void attn_tc(
    const __half* __restrict__ qkv, const float* __restrict__ mask,
    __half* __restrict__ out)
{
    extern __shared__ __align__(16) char asmem[];
    __half* Qs = (__half*)(asmem);                 // 128 x QLD
    __half* Ks = (__half*)(asmem + 6144);
    __half* Vs = (__half*)(asmem + 12288);
    float*  ms = (float*) (asmem + 18432);         // 128
    float*  rs = (float*) (asmem + 18944);         // 128
    float*  Ss = (float*) (asmem + 19456);         // 128 x SLD
    __half* Ps = (__half*)(asmem + 54272);         // 128 x PLD
    float*  Os = (float*) (asmem);                 // aliases Qs/Ks after S phase

    const int h = blockIdx.x & 7;
    const int b = blockIdx.x >> 3;
    const int tid = threadIdx.x, wid = tid >> 5;

    {
        const int row = tid >> 1, ch = tid & 1;
        const __half* base = qkv + ((size_t)b * TT + row) * (3 * DD) + h * HDIM + ch * 8;
        *(uint4*)(Qs + row * QLD + ch * 8) = *(const uint4*)(base);
        *(uint4*)(Ks + row * QLD + ch * 8) = *(const uint4*)(base + DD);
        *(uint4*)(Vs + row * QLD + ch * 8) = *(const uint4*)(base + 2 * DD);
        if (tid < TT) ms[tid] = mask[b * TT + tid];
    }
    __syncthreads();

    wmma::fragment<wmma::matrix_a, 16, 16, 16, __half, wmma::row_major> qf;
    wmma::load_matrix_sync(qf, Qs + wid * 16 * QLD, QLD);

    float sum = 0.f;
    const int er = tid >> 1;
    const int eh = tid & 1;

    for (int chunk = 0; chunk < 2; chunk++) {
#pragma unroll
        for (int j = 0; j < 4; j++) {
            wmma::fragment<wmma::matrix_b, 16, 16, 16, __half, wmma::col_major> kf;
            wmma::fragment<wmma::accumulator, 16, 16, 16, float> sf;
            wmma::load_matrix_sync(kf, Ks + (chunk * 64 + j * 16) * QLD, QLD);
            wmma::fill_fragment(sf, 0.f);
            wmma::mma_sync(sf, qf, kf, sf);
            wmma::store_matrix_sync(Ss + (wid * 16) * SLD + j * 16, sf, SLD, wmma::mem_row_major);
        }
        __syncthreads();
        {
            const float* srow = Ss + er * SLD + eh * 32;
            __half* prow = Ps + er * PLD + chunk * 64 + eh * 32;
            const float* mrow = ms + chunk * 64 + eh * 32;
#pragma unroll
            for (int c = 0; c < 32; c++) {
                float p = fast_exp_s6(fmaf(srow[c], 0.25f, mrow[c]));
                __half ph = __float2half_rn(p);
                prow[c] = ph;
                sum += __half2float(ph);
            }
        }
        __syncthreads();
    }
    sum += __shfl_xor_sync(0xffffffffu, sum, 1);
    if (!eh) rs[er] = sum;
    __syncthreads();

    {
        wmma::fragment<wmma::accumulator, 16, 16, 16, float> of;
        wmma::fill_fragment(of, 0.f);
#pragma unroll
        for (int j = 0; j < 8; j++) {
            wmma::fragment<wmma::matrix_a, 16, 16, 16, __half, wmma::row_major> pf;
            wmma::fragment<wmma::matrix_b, 16, 16, 16, __half, wmma::row_major> vf;
            wmma::load_matrix_sync(pf, Ps + (wid * 16) * PLD + j * 16, PLD);
            wmma::load_matrix_sync(vf, Vs + (j * 16) * QLD, QLD);
            wmma::mma_sync(of, pf, vf, of);
        }
        wmma::store_matrix_sync(Os + (wid * 16) * OLD, of, OLD, wmma::mem_row_major);
    }
    __syncthreads();

    {
        const int r = tid >> 1, c0 = (tid & 1) * 8;
        const float inv = 1.f / rs[r];
        const float* orow = Os + r * OLD + c0;
        uint4 u;
        uint32_t* pu = &u.x;
#pragma unroll
        for (int j = 0; j < 4; j++) {
            __half2 hv = __floats2half2_rn(orow[j * 2] * inv, orow[j * 2 + 1] * inv);
            pu[j] = *reinterpret_cast<uint32_t*>(&hv);
        }
        *(uint4*)(out + ((size_t)b * TT + r) * DD + h * HDIM + c0) = u;
    }
}

// ===========================================================================
// ff_fused (R11, fixed): X <- LN(X + relu(x@W1^T+b1)@W2^T + b2), one CTA per
// 128-token tile, 2 CTA/SM.
// ===========================================================================
#define A_LD    136
#define A_WLD   40
#define F_XS    0
#define F_STG   34816
#define F_HC    69632
#define F_WBUF  88064
#define F_SMEM  108544
#define F_HLD   72

__device__ __forceinline__ void ff_issue(uint32_t sb, const __half* w1,
                                         const __half* w2, int j, int tid)
{
    const int c = j / 6, ph = j % 6;
    const uint32_t wb = sb + F_WBUF + (j & 1) * 10240;
    if (ph < 4) {        // W1 tile: 64 rows x 32k
        int row = tid >> 2, c4 = tid & 3;
        cp16(wb + row * (A_WLD * 2) + c4 * 16,
             w1 + (size_t)(c * 64 + row) * DD + ph * 32 + c4 * 8);
    } else {             // W2 tile: 128 rows x 32k
#pragma unroll
        for (int p = 0; p < 2; p++) {
            int id = p * 256 + tid;
            int row = id >> 2, c4 = id & 3;
            cp16(wb + row * (A_WLD * 2) + c4 * 16,
                 w2 + (size_t)row * FFD + c * 64 + (ph - 4) * 32 + c4 * 8);
        }
    }
    asm volatile("cp.async.commit_group;");
}

__global__ __launch_bounds__(256, 2) void ff_fused(
    const __half* __restrict__ xh, const __half* __restrict__ w1,
    const float* __restrict__ b1, const __half* __restrict__ w2,
    const float* __restrict__ b2,
    float* __restrict__ X, __half* __restrict__ Xh,
    const float* __restrict__ gamma, const float* __restrict__ beta)
{
    extern __shared__ __align__(16) char sm[];
    const uint32_t sb = smem_u32(sm);
    const int tid  = threadIdx.x;
    const int wid  = tid >> 5;
    const int lane = tid & 31;
    const size_t bm = (size_t)blockIdx.x * 128;

    const int wm1 = wid & 3, wn1 = wid >> 2;
    const int wm2 = wid & 1, wn2 = wid >> 1;

    {
#pragma unroll
        for (int p = 0; p < 8; p++) {
            int id = p * 256 + tid;
            int row = id >> 4, c = id & 15;
            cp16(sb + F_XS + row * (A_LD * 2) + c * 16, xh + (bm + row) * DD + c * 8);
        }
        asm volatile("cp.async.commit_group;");
    }
    ff_issue(sb, w1, w2, 0, tid);

    wmma::fragment<wmma::accumulator, 16, 16, 16, float> acc[4][2];
#pragma unroll
    for (int i = 0; i < 4; i++)
#pragma unroll
        for (int jj = 0; jj < 2; jj++) wmma::fill_fragment(acc[i][jj], 0.f);
    wmma::fragment<wmma::accumulator, 16, 16, 16, float> acc1[2][2];

    const __half* Xs = (const __half*)(sm + F_XS);
    float* stg = (float*)(sm + F_STG);
    __half* hc = (__half*)(sm + F_HC);

    for (int j = 0; j < 48; j++) {
        if (j < 47) {
            ff_issue(sb, w1, w2, j + 1, tid);
            asm volatile("cp.async.wait_group 1;");
        } else {
            asm volatile("cp.async.wait_group 0;");
        }
        __syncthreads();

        const int c = j / 6, ph = j % 6;
        const __half* Wb = (const __half*)(sm + F_WBUF + (j & 1) * 10240);
        if (ph < 4) {
            if (ph == 0) {
#pragma unroll
                for (int i = 0; i < 2; i++)
#pragma unroll
                    for (int jj = 0; jj < 2; jj++) wmma::fill_fragment(acc1[i][jj], 0.f);
            }
#pragma unroll
            for (int ks = 0; ks < 2; ks++) {
                wmma::fragment<wmma::matrix_a, 16, 16, 16, __half, wmma::row_major> af[2];
                wmma::fragment<wmma::matrix_b, 16, 16, 16, __half, wmma::col_major> bf[2];
#pragma unroll
                for (int i = 0; i < 2; i++)
                    wmma::load_matrix_sync(af[i], Xs + (wm1 * 32 + i * 16) * A_LD + ph * 32 + ks * 16, A_LD);
#pragma unroll
                for (int jj = 0; jj < 2; jj++)
                    wmma::load_matrix_sync(bf[jj], Wb + (wn1 * 32 + jj * 16) * A_WLD + ks * 16, A_WLD);
#pragma unroll
                for (int i = 0; i < 2; i++)
#pragma unroll
                    for (int jj = 0; jj < 2; jj++)
                        wmma::mma_sync(acc1[i][jj], af[i], bf[jj], acc1[i][jj]);
            }
            if (ph == 3) {
#pragma unroll
                for (int i = 0; i < 2; i++)
#pragma unroll
                    for (int jj = 0; jj < 2; jj++)
                        wmma::store_matrix_sync(stg + (wm1 * 32 + i * 16) * 68 + wn1 * 32 + jj * 16,
                                                acc1[i][jj], 68, wmma::mem_row_major);
                __syncthreads();
                const float* bc = b1 + c * 64;
#pragma unroll
                for (int q = 0; q < 16; q++) {
                    int id = q * 256 + tid;
                    int row = id >> 5, col = (id & 31) * 2;
                    float v0 = fmaxf(stg[row * 68 + col]     + bc[col],     0.f);
                    float v1 = fmaxf(stg[row * 68 + col + 1] + bc[col + 1], 0.f);
                    *(__half2*)(hc + row * F_HLD + col) = __floats2half2_rn(v0, v1);
                }
            }
        } else {
            const int t2 = ph - 4;
#pragma unroll
            for (int ks = 0; ks < 2; ks++) {
                wmma::fragment<wmma::matrix_a, 16, 16, 16, __half, wmma::row_major> af[4];
                wmma::fragment<wmma::matrix_b, 16, 16, 16, __half, wmma::col_major> bf[2];
#pragma unroll
                for (int i = 0; i < 4; i++)
                    wmma::load_matrix_sync(af[i], hc + (wm2 * 64 + i * 16) * F_HLD + t2 * 32 + ks * 16, F_HLD);
#pragma unroll
                for (int jj = 0; jj < 2; jj++)
                    wmma::load_matrix_sync(bf[jj], Wb + (wn2 * 32 + jj * 16) * A_WLD + ks * 16, A_WLD);
#pragma unroll
                for (int i = 0; i < 4; i++)
#pragma unroll
                    for (int jj = 0; jj < 2; jj++)
                        wmma::mma_sync(acc[i][jj], af[i], bf[jj], acc[i][jj]);
            }
        }
        __syncthreads();
    }

    // epilogue: residual + LN (2 passes of 64 rows)
    float* s64 = (float*)(sm + F_STG);
    float4 gv = *(const float4*)(gamma + lane * 4);
    float4 bv = *(const float4*)(beta  + lane * 4);
    float4 bz = *(const float4*)(b2    + lane * 4);
#pragma unroll
    for (int pass = 0; pass < 2; pass++) {
        if (wm2 == pass) {
#pragma unroll
            for (int i = 0; i < 4; i++)
#pragma unroll
                for (int jj = 0; jj < 2; jj++)
                    wmma::store_matrix_sync(s64 + (i * 16) * 132 + wn2 * 32 + jj * 16,
                                            acc[i][jj], 132, wmma::mem_row_major);
        }
        __syncthreads();
#pragma unroll
        for (int rr = 0; rr < 8; rr++) {
            const int r64 = wid * 8 + rr;
            float4 v = *(float4*)(s64 + r64 * 132 + lane * 4);
            const size_t off = (bm + pass * 64 + r64) * DD + lane * 4;
            float4 xv = *(const float4*)(X + off);
            float4 tv;
            tv.x = v.x + bz.x + xv.x; tv.y = v.y + bz.y + xv.y;
            tv.z = v.z + bz.z + xv.z; tv.w = v.w + bz.w + xv.w;
            float s  = tv.x + tv.y + tv.z + tv.w;
            float s2 = tv.x*tv.x + tv.y*tv.y + tv.z*tv.z + tv.w*tv.w;
#pragma unroll
            for (int o = 16; o > 0; o >>= 1) {
                s  += __shfl_xor_sync(0xffffffffu, s,  o);
                s2 += __shfl_xor_sync(0xffffffffu, s2, o);
            }
            float mean = s * (1.f / DD);
            float var  = s2 * (1.f / DD) - mean * mean;
            float rstd = rsqrtf(var + 1e-5f);
            float4 y;
            y.x = (tv.x - mean) * rstd * gv.x + bv.x;
            y.y = (tv.y - mean) * rstd * gv.y + bv.y;
            y.z = (tv.z - mean) * rstd * gv.z + bv.z;
            y.w = (tv.w - mean) * rstd * gv.w + bv.w;
            *(float4*)(X + off) = y;
            __half2 h0 = __floats2half2_rn(y.x, y.y);
            __half2 h1 = __floats2half2_rn(y.z, y.w);
            uint2 u;
            u.x = *reinterpret_cast<uint32_t*>(&h0);
            u.y = *reinterpret_cast<uint32_t*>(&h1);
            *(uint2*)(Xh + off) = u;
        }
        __syncthreads();
    }
}

// ---------------------------------------------------------------------------
extern "C" void kernel_launch(void* const* d_in, const int* in_sizes, int n_in,
                              void* d_out, int out_size)
{
    const float* x_in      = (const float*)d_in[0];
    const float* mask      = (const float*)d_in[1];
    const float* in_proj_w = (const float*)d_in[2];
    const float* in_proj_b = (const float*)d_in[3];
    const float* out_w     = (const float*)d_in[4];
    const float* out_b     = (const float*)d_in[5];
    const float* ln1_g     = (const float*)d_in[6];
    const float* ln1_b     = (const float*)d_in[7];
    const float* ff1_w     = (const float*)d_in[8];
    const float* ff1_b     = (const float*)d_in[9];
    const float* ff2_w     = (const float*)d_in[10];
    const float* ff2_b     = (const float*)d_in[11];
    const float* ln2_g     = (const float*)d_in[12];
    const float* ln2_b     = (const float*)d_in[13];
    float* x = (float*)d_out;

    __half *wqkv, *wout, *wff1, *wff2, *xh, *qkvh, *attnh;
    cudaGetSymbolAddress((void**)&wqkv, g_wqkv);
    cudaGetSymbolAddress((void**)&wout, g_wout);
    cudaGetSymbolAddress((void**)&wff1, g_wff1);
    cudaGetSymbolAddress((void**)&wff2, g_wff2);
    cudaGetSymbolAddress((void**)&xh,   g_xh);
    cudaGetSymbolAddress((void**)&qkvh, g_qkvh);
    cudaGetSymbolAddress((void**)&attnh,g_attnh);

    cudaFuncSetAttribute(gemm_h,   cudaFuncAttributeMaxDynamicSharedMemorySize, SMEM_DYN);
    cudaFuncSetAttribute(attn_tc,  cudaFuncAttributeMaxDynamicSharedMemorySize, ATT_SMEM);
    cudaFuncSetAttribute(ff_fused, cudaFuncAttributeMaxDynamicSharedMemorySize, F_SMEM);

    cudaMemcpyAsync(x, x_in, sizeof(float) * (size_t)MM * DD,
                    cudaMemcpyDeviceToDevice);
    cvt_all<<<(N_CVT + 255) / 256, 256>>>(x_in, in_proj_w, out_w, ff1_w, ff2_w);

    for (int l = 0; l < NL; l++) {
        // qkv = x @ Wqkv^T + b   [MM, 384] fp16
        gemm_h<<<dim3(3, MM / 128), 256, SMEM_DYN>>>(
            xh, wqkv + (size_t)l * 3 * DD * DD, in_proj_b + (size_t)l * 3 * DD,
            qkvh, nullptr, nullptr, nullptr, nullptr, 3 * DD, DD, 0);
        // attention -> attnh [MM, DD] fp16 (tensor-core)
        attn_tc<<<BB * HH, 256, ATT_SMEM>>>(qkvh, mask, attnh);
        // x = LN(x + attnh @ out_w^T + out_b); xh mirror
        gemm_h<<<dim3(1, MM / 128), 256, SMEM_DYN>>>(
            attnh, wout + (size_t)l * DD * DD, out_b + (size_t)l * DD,
            nullptr, x, xh, ln1_g + (size_t)l * DD, ln1_b + (size_t)l * DD, DD, DD, 2);
        // x = LN(x + relu(x@W1^T+b1)@W2^T + b2); xh mirror (fused FF)
        ff_fused<<<MM / 128, 256, F_SMEM>>>(
            xh, wff1 + (size_t)l * FFD * DD, ff1_b + (size_t)l * FFD,
            wff2 + (size_t)l * DD * FFD, ff2_b + (size_t)l * DD,
            x, xh, ln2_g + (size_t)l * DD, ln2_b + (size_t)l * DD);
    }
}

// round 13
// speedup vs baseline: 1.4568x; 1.4568x over previous
#include <cuda_runtime.h>
#include <cuda_fp16.h>
#include <mma.h>
#include <cstdint>
using namespace nvcuda;

// Problem dims (fixed)
#define BB   1024
#define TT   128
#define DD   128
#define HH   8
#define HDIM 16
#define FFD  512
#define NL   2
#define MM   (BB*TT)          // 131072 tokens

// fp16 scratch
__device__ __half g_wqkv[(size_t)NL * 3 * DD * DD];
__device__ __half g_wout[(size_t)NL * DD * DD];
__device__ __half g_wff1[(size_t)NL * FFD * DD];
__device__ __half g_wff2[(size_t)NL * DD * FFD];
__device__ __half g_xh  [(size_t)MM * DD];
__device__ __half g_qkvh[(size_t)MM * 3 * DD];
__device__ __half g_attnh[(size_t)MM * DD];

// ---------------------------------------------------------------------------
#define N_XH4 (MM * DD / 4)
#define N_WQ4 (NL * 3 * DD * DD / 4)
#define N_WO4 (NL * DD * DD / 4)
#define N_W14 (NL * FFD * DD / 4)
#define N_W24 (NL * DD * FFD / 4)
#define N_CVT (N_XH4 + N_WQ4 + N_WO4 + N_W14 + N_W24)

__global__ void cvt_all(const float* __restrict__ x,
                        const float* __restrict__ wq,
                        const float* __restrict__ wo,
                        const float* __restrict__ w1,
                        const float* __restrict__ w2)
{
    long i = (long)blockIdx.x * blockDim.x + threadIdx.x;
    if (i >= N_CVT) return;
    const float* src;
    __half* dst;
    long off = i;
    if (off < N_XH4)                      { src = x;  dst = g_xh;   }
    else if ((off -= N_XH4) < N_WQ4)      { src = wq; dst = g_wqkv; }
    else if ((off -= N_WQ4) < N_WO4)      { src = wo; dst = g_wout; }
    else if ((off -= N_WO4) < N_W14)      { src = w1; dst = g_wff1; }
    else  { off -= N_W14;                   src = w2; dst = g_wff2; }
    float4 v = ((const float4*)src)[off];
    __half2 h0 = __floats2half2_rn(v.x, v.y);
    __half2 h1 = __floats2half2_rn(v.z, v.w);
    uint2 u;
    u.x = *reinterpret_cast<uint32_t*>(&h0);
    u.y = *reinterpret_cast<uint32_t*>(&h1);
    ((uint2*)dst)[off] = u;
}

__device__ __forceinline__ uint32_t smem_u32(const void* p) {
    uint32_t a;
    asm("{ .reg .u64 t; cvta.to.shared.u64 t, %1; cvt.u32.u64 %0, t; }"
        : "=r"(a) : "l"(p));
    return a;
}
__device__ __forceinline__ void cp16(uint32_t dst, const void* src) {
    asm volatile("cp.async.ca.shared.global [%0], [%1], 16;" :: "r"(dst), "l"(src));
}
__device__ __forceinline__ float fast_exp_s6(float x) {
    x = fmaxf(x, -80.f);
    float t  = x * 1.4426950408889634f;
    float fn = t + 12582912.f;
    int   ni = __float_as_int(fn) - 0x4B400000;
    float r  = t - (fn - 12582912.f);
    float p  = 0.00133336f;
    p = fmaf(p, r, 0.00961813f);
    p = fmaf(p, r, 0.05550411f);
    p = fmaf(p, r, 0.24022651f);
    p = fmaf(p, r, 0.69314718f);
    p = fmaf(p, r, 1.0f);
    return p * __int_as_float((ni + 121) << 23);   // * 2^(n-6)
}

// ---------------------------------------------------------------------------
// gemm_h: qkv (mode 0) + out-proj + LN1 (mode 2).
// ---------------------------------------------------------------------------
#define BK   32
#define ALD  40
#define STG_B 20480
#define NS   4
#define CLD  132
#define SMEM_DYN (NS*STG_B)

__global__ __launch_bounds__(256, 2) void gemm_h(
    const __half* __restrict__ A, const __half* __restrict__ W,
    const float* __restrict__ bias,
    __half* __restrict__ Ch,
    float* __restrict__ X, __half* __restrict__ Xh,
    const float* __restrict__ gamma, const float* __restrict__ beta,
    int N, int K, int mode)
{
    extern __shared__ __align__(16) char smem[];
    const uint32_t sbase = smem_u32(smem);
    const int tid  = threadIdx.x;
    const int wid  = tid >> 5;
    const int lane = tid & 31;
    const int wm   = wid & 1;
    const int wn   = wid >> 1;
    const size_t bm = (size_t)blockIdx.y * 128;
    const size_t bn = (size_t)blockIdx.x * 128;
    const int NT = K / BK;

    const int rA0 = tid >> 2, cA0 = tid & 3;
    const int rA1 = (tid + 256) >> 2, cA1 = (tid + 256) & 3;

    wmma::fragment<wmma::accumulator, 16, 16, 16, float> acc[4][2];
#pragma unroll
    for (int i = 0; i < 4; i++)
#pragma unroll
        for (int j = 0; j < 2; j++) wmma::fill_fragment(acc[i][j], 0.f);

#pragma unroll
    for (int t = 0; t < NS - 1; t++) {
        if (t < NT) {
            const int kk = t * BK;
            const uint32_t sb = sbase + (t % NS) * STG_B;
            cp16(sb + (rA0 * ALD + cA0 * 8) * 2, A + (bm + rA0) * K + kk + cA0 * 8);
            cp16(sb + (rA1 * ALD + cA1 * 8) * 2, A + (bm + rA1) * K + kk + cA1 * 8);
            cp16(sb + 10240 + (rA0 * ALD + cA0 * 8) * 2, W + (bn + rA0) * K + kk + cA0 * 8);
            cp16(sb + 10240 + (rA1 * ALD + cA1 * 8) * 2, W + (bn + rA1) * K + kk + cA1 * 8);
        }
        asm volatile("cp.async.commit_group;");
    }

    for (int t = 0; t < NT; t++) {
        asm volatile("cp.async.wait_group %0;" :: "n"(NS - 2));
        __syncthreads();
        {
            const __half* As = (const __half*)(smem + (t % NS) * STG_B);
            const __half* Ws = As + 5120;
#pragma unroll
            for (int ks = 0; ks < 2; ks++) {
                wmma::fragment<wmma::matrix_a, 16, 16, 16, __half, wmma::row_major> af[4];
                wmma::fragment<wmma::matrix_b, 16, 16, 16, __half, wmma::col_major> bf[2];
#pragma unroll
                for (int i = 0; i < 4; i++)
                    wmma::load_matrix_sync(af[i], As + (wm * 64 + i * 16) * ALD + ks * 16, ALD);
#pragma unroll
                for (int j = 0; j < 2; j++)
                    wmma::load_matrix_sync(bf[j], Ws + (wn * 32 + j * 16) * ALD + ks * 16, ALD);
#pragma unroll
                for (int i = 0; i < 4; i++)
#pragma unroll
                    for (int j = 0; j < 2; j++)
                        wmma::mma_sync(acc[i][j], af[i], bf[j], acc[i][j]);
            }
        }
        __syncthreads();
        {
            const int tn = t + NS - 1;
            if (tn < NT) {
                const int kk = tn * BK;
                const uint32_t sb = sbase + (tn % NS) * STG_B;
                cp16(sb + (rA0 * ALD + cA0 * 8) * 2, A + (bm + rA0) * K + kk + cA0 * 8);
                cp16(sb + (rA1 * ALD + cA1 * 8) * 2, A + (bm + rA1) * K + kk + cA1 * 8);
                cp16(sb + 10240 + (rA0 * ALD + cA0 * 8) * 2, W + (bn + rA0) * K + kk + cA0 * 8);
                cp16(sb + 10240 + (rA1 * ALD + cA1 * 8) * 2, W + (bn + rA1) * K + kk + cA1 * 8);
            }
            asm volatile("cp.async.commit_group;");
        }
    }

    float* smf = (float*)smem;
#pragma unroll
    for (int i = 0; i < 4; i++)
#pragma unroll
        for (int j = 0; j < 2; j++)
            wmma::store_matrix_sync(smf + (wm * 64 + i * 16) * CLD + wn * 32 + j * 16,
                                    acc[i][j], CLD, wmma::mem_row_major);
    __syncthreads();

    if (mode == 2) {
        float4 gv = *(const float4*)(gamma + lane * 4);
        float4 bv = *(const float4*)(beta  + lane * 4);
        float4 bz = *(const float4*)(bias  + lane * 4);
#pragma unroll
        for (int i = 0; i < 16; i++) {
            const int row = wid * 16 + i;
            float4 v = *(float4*)(smf + row * CLD + lane * 4);
            const size_t off = (bm + row) * DD + lane * 4;
            float4 xv = *(const float4*)(X + off);
            float4 tv;
            tv.x = v.x + bz.x + xv.x; tv.y = v.y + bz.y + xv.y;
            tv.z = v.z + bz.z + xv.z; tv.w = v.w + bz.w + xv.w;
            float s  = tv.x + tv.y + tv.z + tv.w;
            float s2 = tv.x*tv.x + tv.y*tv.y + tv.z*tv.z + tv.w*tv.w;
#pragma unroll
            for (int o = 16; o > 0; o >>= 1) {
                s  += __shfl_xor_sync(0xffffffffu, s,  o);
                s2 += __shfl_xor_sync(0xffffffffu, s2, o);
            }
            float mean = s * (1.f / DD);
            float var  = s2 * (1.f / DD) - mean * mean;
            float rstd = rsqrtf(var + 1e-5f);
            float4 y;
            y.x = (tv.x - mean) * rstd * gv.x + bv.x;
            y.y = (tv.y - mean) * rstd * gv.y + bv.y;
            y.z = (tv.z - mean) * rstd * gv.z + bv.z;
            y.w = (tv.w - mean) * rstd * gv.w + bv.w;
            *(float4*)(X + off) = y;
            __half2 h0 = __floats2half2_rn(y.x, y.y);
            __half2 h1 = __floats2half2_rn(y.z, y.w);
            uint2 u;
            u.x = *reinterpret_cast<uint32_t*>(&h0);
            u.y = *reinterpret_cast<uint32_t*>(&h1);
            *(uint2*)(Xh + off) = u;
        }
    } else {
#pragma unroll
        for (int i = 0; i < 16; i++) {
            int idx = i * 256 + tid;
            int row = idx >> 5;
            int cc  = (idx & 31) * 4;
            float4 v  = *(float4*)(smf + row * CLD + cc);
            float4 bz = *(const float4*)(bias + bn + cc);
            v.x += bz.x; v.y += bz.y; v.z += bz.z; v.w += bz.w;
            __half2 h0 = __floats2half2_rn(v.x, v.y);
            __half2 h1 = __floats2half2_rn(v.z, v.w);
            uint2 u;
            u.x = *reinterpret_cast<uint32_t*>(&h0);
            u.y = *reinterpret_cast<uint32_t*>(&h1);
            *(uint2*)(Ch + (bm + row) * N + bn + cc) = u;
        }
    }
}

// ---------------------------------------------------------------------------
// attn_tc: one block per (b,h), 256 threads / 8 warps, 2 CTA/SM.
// ---------------------------------------------------------------------------
#define QLD 24
#define SLD 68
#define PLD 136
#define OLD 20
#define ATT_SMEM 89088

__global__ __launch_bounds__(256, 2) void attn_tc(
    const __half* __restrict__ qkv, const float* __restrict__ mask,
    __half* __restrict__ out)
{
    extern __shared__ __align__(16) char asmem[];
    __half* Qs = (__half*)(asmem);
    __half* Ks = (__half*)(asmem + 6144);
    __half* Vs = (__half*)(asmem + 12288);
    float*  ms = (float*) (asmem + 18432);
    float*  rs = (float*) (asmem + 18944);
    float*  Ss = (float*) (asmem + 19456);
    __half* Ps = (__half*)(asmem + 54272);
    float*  Os = (float*) (asmem);

    const int h = blockIdx.x & 7;
    const int b = blockIdx.x >> 3;
    const int tid = threadIdx.x, wid = tid >> 5;

    {
        const int row = tid >> 1, ch = tid & 1;
        const __half* base = qkv + ((size_t)b * TT + row) * (3 * DD) + h * HDIM + ch * 8;
        *(uint4*)(Qs + row * QLD + ch * 8) = *(const uint4*)(base);
        *(uint4*)(Ks + row * QLD + ch * 8) = *(const uint4*)(base + DD);
        *(uint4*)(Vs + row * QLD + ch * 8) = *(const uint4*)(base + 2 * DD);
        if (tid < TT) ms[tid] = mask[b * TT + tid];
    }
    __syncthreads();

    wmma::fragment<wmma::matrix_a, 16, 16, 16, __half, wmma::row_major> qf;
    wmma::load_matrix_sync(qf, Qs + wid * 16 * QLD, QLD);

    float sum = 0.f;
    const int er = tid >> 1;
    const int eh = tid & 1;

    for (int chunk = 0; chunk < 2; chunk++) {
#pragma unroll
        for (int j = 0; j < 4; j++) {
            wmma::fragment<wmma::matrix_b, 16, 16, 16, __half, wmma::col_major> kf;
            wmma::fragment<wmma::accumulator, 16, 16, 16, float> sf;
            wmma::load_matrix_sync(kf, Ks + (chunk * 64 + j * 16) * QLD, QLD);
            wmma::fill_fragment(sf, 0.f);
            wmma::mma_sync(sf, qf, kf, sf);
            wmma::store_matrix_sync(Ss + (wid * 16) * SLD + j * 16, sf, SLD, wmma::mem_row_major);
        }
        __syncthreads();
        {
            const float* srow = Ss + er * SLD + eh * 32;
            __half* prow = Ps + er * PLD + chunk * 64 + eh * 32;
            const float* mrow = ms + chunk * 64 + eh * 32;
#pragma unroll
            for (int c = 0; c < 32; c++) {
                float p = fast_exp_s6(fmaf(srow[c], 0.25f, mrow[c]));
                __half ph = __float2half_rn(p);
                prow[c] = ph;
                sum += __half2float(ph);
            }
        }
        __syncthreads();
    }
    sum += __shfl_xor_sync(0xffffffffu, sum, 1);
    if (!eh) rs[er] = sum;
    __syncthreads();

    {
        wmma::fragment<wmma::accumulator, 16, 16, 16, float> of;
        wmma::fill_fragment(of, 0.f);
#pragma unroll
        for (int j = 0; j < 8; j++) {
            wmma::fragment<wmma::matrix_a, 16, 16, 16, __half, wmma::row_major> pf;
            wmma::fragment<wmma::matrix_b, 16, 16, 16, __half, wmma::row_major> vf;
            wmma::load_matrix_sync(pf, Ps + (wid * 16) * PLD + j * 16, PLD);
            wmma::load_matrix_sync(vf, Vs + (j * 16) * QLD, QLD);
            wmma::mma_sync(of, pf, vf, of);
        }
        wmma::store_matrix_sync(Os + (wid * 16) * OLD, of, OLD, wmma::mem_row_major);
    }
    __syncthreads();

    {
        const int r = tid >> 1, c0 = (tid & 1) * 8;
        const float inv = 1.f / rs[r];
        const float* orow = Os + r * OLD + c0;
        uint4 u;
        uint32_t* pu = &u.x;
#pragma unroll
        for (int j = 0; j < 4; j++) {
            __half2 hv = __floats2half2_rn(orow[j * 2] * inv, orow[j * 2 + 1] * inv);
            pu[j] = *reinterpret_cast<uint32_t*>(&hv);
        }
        *(uint4*)(out + ((size_t)b * TT + r) * DD + h * HDIM + c0) = u;
    }
}

// ===========================================================================
// ff_fused (indexing-optimized): X <- LN(X + relu(x@W1^T+b1)@W2^T + b2)
// ===========================================================================
#define A_LD    136
#define A_WLD   40
#define F_XS    0
#define F_STG   34816
#define F_HC    69632
#define F_WBUF  88064
#define F_SMEM  108544
#define F_HLD   72

__global__ __launch_bounds__(256, 2) void ff_fused(
    const __half* __restrict__ xh, const __half* __restrict__ w1,
    const float* __restrict__ b1, const __half* __restrict__ w2,
    const float* __restrict__ b2,
    float* __restrict__ X, __half* __restrict__ Xh,
    const float* __restrict__ gamma, const float* __restrict__ beta)
{
    extern __shared__ __align__(16) char sm[];
    const uint32_t sb = smem_u32(sm);
    const int tid  = threadIdx.x;
    const int wid  = tid >> 5;
    const int lane = tid & 31;
    const size_t bm = (size_t)blockIdx.x * 128;

    const int wm1 = wid & 3, wn1 = wid >> 2;
    const int wm2 = wid & 1, wn2 = wid >> 1;

    // hoisted per-thread cp.async state
    const int r1 = tid >> 2, c4 = tid & 3;               // W1: row 0..63, chunk
    const uint32_t wdst0 = (r1 * A_WLD + c4 * 8) * 2;    // smem offset within buf
    const uint32_t wdst1 = ((r1 + 64) * A_WLD + c4 * 8) * 2;
    const __half* w1p = w1 + (size_t)r1 * DD + c4 * 8;           // + c*64*DD + ph*32
    const __half* w2p0 = w2 + (size_t)r1 * FFD + c4 * 8;         // + c*64 + t2*32
    const __half* w2p1 = w2 + (size_t)(r1 + 64) * FFD + c4 * 8;

    {
#pragma unroll
        for (int p = 0; p < 8; p++) {
            int id = p * 256 + tid;
            int row = id >> 4, c = id & 15;
            cp16(sb + F_XS + row * (A_LD * 2) + c * 16, xh + (bm + row) * DD + c * 8);
        }
        asm volatile("cp.async.commit_group;");
    }
    // issue j=0 (c=0, ph=0): W1 tile
    cp16(sb + F_WBUF + wdst0, w1p);
    asm volatile("cp.async.commit_group;");

    wmma::fragment<wmma::accumulator, 16, 16, 16, float> acc[4][2];
#pragma unroll
    for (int i = 0; i < 4; i++)
#pragma unroll
        for (int jj = 0; jj < 2; jj++) wmma::fill_fragment(acc[i][jj], 0.f);
    wmma::fragment<wmma::accumulator, 16, 16, 16, float> acc1[2][2];

    const __half* Xs = (const __half*)(sm + F_XS);
    float* stg = (float*)(sm + F_STG);
    __half* hc = (__half*)(sm + F_HC);

    int cn = 0, phn = 0;       // next-issue counters (track j+1)
    for (int j = 0; j < 48; j++) {
        const int c = cn, ph = phn;
        if (j < 47) {
            // advance to j+1 and issue
            if (++phn == 6) { phn = 0; cn++; }
            const uint32_t wb = sb + F_WBUF + ((j + 1) & 1) * 10240;
            if (phn < 4) {
                cp16(wb + wdst0, w1p + (size_t)cn * 64 * DD + phn * 32);
            } else {
                const int t2 = phn - 4;
                cp16(wb + wdst0, w2p0 + cn * 64 + t2 * 32);
                cp16(wb + wdst1, w2p1 + cn * 64 + t2 * 32);
            }
            asm volatile("cp.async.commit_group;");
            asm volatile("cp.async.wait_group 1;");
        } else {
            asm volatile("cp.async.wait_group 0;");
        }
        __syncthreads();

        const __half* Wb = (const __half*)(sm + F_WBUF + (j & 1) * 10240);
        if (ph < 4) {
            if (ph == 0) {
#pragma unroll
                for (int i = 0; i < 2; i++)
#pragma unroll
                    for (int jj = 0; jj < 2; jj++) wmma::fill_fragment(acc1[i][jj], 0.f);
            }
#pragma unroll
            for (int ks = 0; ks < 2; ks++) {
                wmma::fragment<wmma::matrix_a, 16, 16, 16, __half, wmma::row_major> af[2];
                wmma::fragment<wmma::matrix_b, 16, 16, 16, __half, wmma::col_major> bf[2];
#pragma unroll
                for (int i = 0; i < 2; i++)
                    wmma::load_matrix_sync(af[i], Xs + (wm1 * 32 + i * 16) * A_LD + ph * 32 + ks * 16, A_LD);
#pragma unroll
                for (int jj = 0; jj < 2; jj++)
                    wmma::load_matrix_sync(bf[jj], Wb + (wn1 * 32 + jj * 16) * A_WLD + ks * 16, A_WLD);
#pragma unroll
                for (int i = 0; i < 2; i++)
#pragma unroll
                    for (int jj = 0; jj < 2; jj++)
                        wmma::mma_sync(acc1[i][jj], af[i], bf[jj], acc1[i][jj]);
            }
            if (ph == 3) {
#pragma unroll
                for (int i = 0; i < 2; i++)
#pragma unroll
                    for (int jj = 0; jj < 2; jj++)
                        wmma::store_matrix_sync(stg + (wm1 * 32 + i * 16) * 68 + wn1 * 32 + jj * 16,
                                                acc1[i][jj], 68, wmma::mem_row_major);
                __syncthreads();
                const float* bc = b1 + c * 64;
#pragma unroll
                for (int q = 0; q < 16; q++) {
                    int id = q * 256 + tid;
                    int row = id >> 5, col = (id & 31) * 2;
                    float v0 = fmaxf(stg[row * 68 + col]     + bc[col],     0.f);
                    float v1 = fmaxf(stg[row * 68 + col + 1] + bc[col + 1], 0.f);
                    *(__half2*)(hc + row * F_HLD + col) = __floats2half2_rn(v0, v1);
                }
            }
        } else {
            const int t2 = ph - 4;
#pragma unroll
            for (int ks = 0; ks < 2; ks++) {
                wmma::fragment<wmma::matrix_a, 16, 16, 16, __half, wmma::row_major> af[4];
                wmma::fragment<wmma::matrix_b, 16, 16, 16, __half, wmma::col_major> bf[2];
#pragma unroll
                for (int i = 0; i < 4; i++)
                    wmma::load_matrix_sync(af[i], hc + (wm2 * 64 + i * 16) * F_HLD + t2 * 32 + ks * 16, F_HLD);
#pragma unroll
                for (int jj = 0; jj < 2; jj++)
                    wmma::load_matrix_sync(bf[jj], Wb + (wn2 * 32 + jj * 16) * A_WLD + ks * 16, A_WLD);
#pragma unroll
                for (int i = 0; i < 4; i++)
#pragma unroll
                    for (int jj = 0; jj < 2; jj++)
                        wmma::mma_sync(acc[i][jj], af[i], bf[jj], acc[i][jj]);
            }
        }
        __syncthreads();
    }

    // epilogue: residual + LN (2 passes of 64 rows)
    float* s64 = (float*)(sm + F_STG);
    float4 gv = *(const float4*)(gamma + lane * 4);
    float4 bv = *(const float4*)(beta  + lane * 4);
    float4 bz = *(const float4*)(b2    + lane * 4);
#pragma unroll
    for (int pass = 0; pass < 2; pass++) {
        if (wm2 == pass) {
#pragma unroll
            for (int i = 0; i < 4; i++)
#pragma unroll
                for (int jj = 0; jj < 2; jj++)
                    wmma::store_matrix_sync(s64 + (i * 16) * 132 + wn2 * 32 + jj * 16,
                                            acc[i][jj], 132, wmma::mem_row_major);
        }
        __syncthreads();
#pragma unroll
        for (int rr = 0; rr < 8; rr++) {
            const int r64 = wid * 8 + rr;
            float4 v = *(float4*)(s64 + r64 * 132 + lane * 4);
            const size_t off = (bm + pass * 64 + r64) * DD + lane * 4;
            float4 xv = *(const float4*)(X + off);
            float4 tv;
            tv.x = v.x + bz.x + xv.x; tv.y = v.y + bz.y + xv.y;
            tv.z = v.z + bz.z + xv.z; tv.w = v.w + bz.w + xv.w;
            float s  = tv.x + tv.y + tv.z + tv.w;
            float s2 = tv.x*tv.x + tv.y*tv.y + tv.z*tv.z + tv.w*tv.w;
#pragma unroll
            for (int o = 16; o > 0; o >>= 1) {
                s  += __shfl_xor_sync(0xffffffffu, s,  o);
                s2 += __shfl_xor_sync(0xffffffffu, s2, o);
            }
            float mean = s * (1.f / DD);
            float var  = s2 * (1.f / DD) - mean * mean;
            float rstd = rsqrtf(var + 1e-5f);
            float4 y;
            y.x = (tv.x - mean) * rstd * gv.x + bv.x;
            y.y = (tv.y - mean) * rstd * gv.y + bv.y;
            y.z = (tv.z - mean) * rstd * gv.z + bv.z;
            y.w = (tv.w - mean) * rstd * gv.w + bv.w;
            *(float4*)(X + off) = y;
            __half2 h0 = __floats2half2_rn(y.x, y.y);
            __half2 h1 = __floats2half2_rn(y.z, y.w);
            uint2 u;
            u.x = *reinterpret_cast<uint32_t*>(&h0);
            u.y = *reinterpret_cast<uint32_t*>(&h1);
            *(uint2*)(Xh + off) = u;
        }
        __syncthreads();
    }
}

// ---------------------------------------------------------------------------
extern "C" void kernel_launch(void* const* d_in, const int* in_sizes, int n_in,
                              void* d_out, int out_size)
{
    const float* x_in      = (const float*)d_in[0];
    const float* mask      = (const float*)d_in[1];
    const float* in_proj_w = (const float*)d_in[2];
    const float* in_proj_b = (const float*)d_in[3];
    const float* out_w     = (const float*)d_in[4];
    const float* out_b     = (const float*)d_in[5];
    const float* ln1_g     = (const float*)d_in[6];
    const float* ln1_b     = (const float*)d_in[7];
    const float* ff1_w     = (const float*)d_in[8];
    const float* ff1_b     = (const float*)d_in[9];
    const float* ff2_w     = (const float*)d_in[10];
    const float* ff2_b     = (const float*)d_in[11];
    const float* ln2_g     = (const float*)d_in[12];
    const float* ln2_b     = (const float*)d_in[13];
    float* x = (float*)d_out;

    __half *wqkv, *wout, *wff1, *wff2, *xh, *qkvh, *attnh;
    cudaGetSymbolAddress((void**)&wqkv, g_wqkv);
    cudaGetSymbolAddress((void**)&wout, g_wout);
    cudaGetSymbolAddress((void**)&wff1, g_wff1);
    cudaGetSymbolAddress((void**)&wff2, g_wff2);
    cudaGetSymbolAddress((void**)&xh,   g_xh);
    cudaGetSymbolAddress((void**)&qkvh, g_qkvh);
    cudaGetSymbolAddress((void**)&attnh,g_attnh);

    cudaFuncSetAttribute(gemm_h,   cudaFuncAttributeMaxDynamicSharedMemorySize, SMEM_DYN);
    cudaFuncSetAttribute(attn_tc,  cudaFuncAttributeMaxDynamicSharedMemorySize, ATT_SMEM);
    cudaFuncSetAttribute(ff_fused, cudaFuncAttributeMaxDynamicSharedMemorySize, F_SMEM);

    cudaMemcpyAsync(x, x_in, sizeof(float) * (size_t)MM * DD,
                    cudaMemcpyDeviceToDevice);
    cvt_all<<<(N_CVT + 255) / 256, 256>>>(x_in, in_proj_w, out_w, ff1_w, ff2_w);

    for (int l = 0; l < NL; l++) {
        gemm_h<<<dim3(3, MM / 128), 256, SMEM_DYN>>>(
            xh, wqkv + (size_t)l * 3 * DD * DD, in_proj_b + (size_t)l * 3 * DD,
            qkvh, nullptr, nullptr, nullptr, nullptr, 3 * DD, DD, 0);
        attn_tc<<<BB * HH, 256, ATT_SMEM>>>(qkvh, mask, attnh);
        gemm_h<<<dim3(1, MM / 128), 256, SMEM_DYN>>>(
            attnh, wout + (size_t)l * DD * DD, out_b + (size_t)l * DD,
            nullptr, x, xh, ln1_g + (size_t)l * DD, ln1_b + (size_t)l * DD, DD, DD, 2);
        ff_fused<<<MM / 128, 256, F_SMEM>>>(
            xh, wff1 + (size_t)l * FFD * DD, ff1_b + (size_t)l * FFD,
            wff2 + (size_t)l * DD * FFD, ff2_b + (size_t)l * DD,
            x, xh, ln2_g + (size_t)l * DD, ln2_b + (size_t)l * DD);
    }
}

// round 14
// speedup vs baseline: 1.5946x; 1.0946x over previous
#include <cuda_runtime.h>
#include <cuda_fp16.h>
#include <mma.h>
#include <cstdint>
using namespace nvcuda;

// Problem dims (fixed)
#define BB   1024
#define TT   128
#define DD   128
#define HH   8
#define HDIM 16
#define FFD  512
#define NL   2
#define MM   (BB*TT)          // 131072 tokens

// fp16 scratch
__device__ __half g_wqkv[(size_t)NL * 3 * DD * DD];
__device__ __half g_wout[(size_t)NL * DD * DD];
__device__ __half g_wff1[(size_t)NL * FFD * DD];
__device__ __half g_wff2[(size_t)NL * DD * FFD];
__device__ __half g_xh  [(size_t)MM * DD];
__device__ __half g_qkvh[(size_t)MM * 3 * DD];
__device__ __half g_attnh[(size_t)MM * DD];

// ---------------------------------------------------------------------------
#define N_XH4 (MM * DD / 4)
#define N_WQ4 (NL * 3 * DD * DD / 4)
#define N_WO4 (NL * DD * DD / 4)
#define N_W14 (NL * FFD * DD / 4)
#define N_W24 (NL * DD * FFD / 4)
#define N_CVT (N_XH4 + N_WQ4 + N_WO4 + N_W14 + N_W24)

__global__ void cvt_all(const float* __restrict__ x,
                        const float* __restrict__ wq,
                        const float* __restrict__ wo,
                        const float* __restrict__ w1,
                        const float* __restrict__ w2)
{
    long i = (long)blockIdx.x * blockDim.x + threadIdx.x;
    if (i >= N_CVT) return;
    const float* src;
    __half* dst;
    long off = i;
    if (off < N_XH4)                      { src = x;  dst = g_xh;   }
    else if ((off -= N_XH4) < N_WQ4)      { src = wq; dst = g_wqkv; }
    else if ((off -= N_WQ4) < N_WO4)      { src = wo; dst = g_wout; }
    else if ((off -= N_WO4) < N_W14)      { src = w1; dst = g_wff1; }
    else  { off -= N_W14;                   src = w2; dst = g_wff2; }
    float4 v = ((const float4*)src)[off];
    __half2 h0 = __floats2half2_rn(v.x, v.y);
    __half2 h1 = __floats2half2_rn(v.z, v.w);
    uint2 u;
    u.x = *reinterpret_cast<uint32_t*>(&h0);
    u.y = *reinterpret_cast<uint32_t*>(&h1);
    ((uint2*)dst)[off] = u;
}

__device__ __forceinline__ uint32_t smem_u32(const void* p) {
    uint32_t a;
    asm("{ .reg .u64 t; cvta.to.shared.u64 t, %1; cvt.u32.u64 %0, t; }"
        : "=r"(a) : "l"(p));
    return a;
}
__device__ __forceinline__ void cp16(uint32_t dst, const void* src) {
    asm volatile("cp.async.ca.shared.global [%0], [%1], 16;" :: "r"(dst), "l"(src));
}
__device__ __forceinline__ float fast_exp_s6(float x) {
    x = fmaxf(x, -80.f);
    float t  = x * 1.4426950408889634f;
    float fn = t + 12582912.f;
    int   ni = __float_as_int(fn) - 0x4B400000;
    float r  = t - (fn - 12582912.f);
    float p  = 0.00133336f;
    p = fmaf(p, r, 0.00961813f);
    p = fmaf(p, r, 0.05550411f);
    p = fmaf(p, r, 0.24022651f);
    p = fmaf(p, r, 0.69314718f);
    p = fmaf(p, r, 1.0f);
    return p * __int_as_float((ni + 121) << 23);   // * 2^(n-6)
}

// ---------------------------------------------------------------------------
// gemm_h: qkv (mode 0) + out-proj + LN1 (mode 2: residual from fp16 Xh).
// ---------------------------------------------------------------------------
#define BK   32
#define ALD  40
#define STG_B 20480
#define NS   4
#define CLD  132
#define SMEM_DYN (NS*STG_B)

__global__ __launch_bounds__(256, 2) void gemm_h(
    const __half* __restrict__ A, const __half* __restrict__ W,
    const float* __restrict__ bias,
    __half* __restrict__ Ch,
    float* __restrict__ X, __half* __restrict__ Xh,
    const float* __restrict__ gamma, const float* __restrict__ beta,
    int N, int K, int mode, int wx)
{
    extern __shared__ __align__(16) char smem[];
    const uint32_t sbase = smem_u32(smem);
    const int tid  = threadIdx.x;
    const int wid  = tid >> 5;
    const int lane = tid & 31;
    const int wm   = wid & 1;
    const int wn   = wid >> 1;
    const size_t bm = (size_t)blockIdx.y * 128;
    const size_t bn = (size_t)blockIdx.x * 128;
    const int NT = K / BK;

    const int rA0 = tid >> 2, cA0 = tid & 3;
    const int rA1 = (tid + 256) >> 2, cA1 = (tid + 256) & 3;

    wmma::fragment<wmma::accumulator, 16, 16, 16, float> acc[4][2];
#pragma unroll
    for (int i = 0; i < 4; i++)
#pragma unroll
        for (int j = 0; j < 2; j++) wmma::fill_fragment(acc[i][j], 0.f);

#pragma unroll
    for (int t = 0; t < NS - 1; t++) {
        if (t < NT) {
            const int kk = t * BK;
            const uint32_t sb = sbase + (t % NS) * STG_B;
            cp16(sb + (rA0 * ALD + cA0 * 8) * 2, A + (bm + rA0) * K + kk + cA0 * 8);
            cp16(sb + (rA1 * ALD + cA1 * 8) * 2, A + (bm + rA1) * K + kk + cA1 * 8);
            cp16(sb + 10240 + (rA0 * ALD + cA0 * 8) * 2, W + (bn + rA0) * K + kk + cA0 * 8);
            cp16(sb + 10240 + (rA1 * ALD + cA1 * 8) * 2, W + (bn + rA1) * K + kk + cA1 * 8);
        }
        asm volatile("cp.async.commit_group;");
    }

    for (int t = 0; t < NT; t++) {
        asm volatile("cp.async.wait_group %0;" :: "n"(NS - 2));
        __syncthreads();
        {
            const __half* As = (const __half*)(smem + (t % NS) * STG_B);
            const __half* Ws = As + 5120;
#pragma unroll
            for (int ks = 0; ks < 2; ks++) {
                wmma::fragment<wmma::matrix_a, 16, 16, 16, __half, wmma::row_major> af[4];
                wmma::fragment<wmma::matrix_b, 16, 16, 16, __half, wmma::col_major> bf[2];
#pragma unroll
                for (int i = 0; i < 4; i++)
                    wmma::load_matrix_sync(af[i], As + (wm * 64 + i * 16) * ALD + ks * 16, ALD);
#pragma unroll
                for (int j = 0; j < 2; j++)
                    wmma::load_matrix_sync(bf[j], Ws + (wn * 32 + j * 16) * ALD + ks * 16, ALD);
#pragma unroll
                for (int i = 0; i < 4; i++)
#pragma unroll
                    for (int j = 0; j < 2; j++)
                        wmma::mma_sync(acc[i][j], af[i], bf[j], acc[i][j]);
            }
        }
        __syncthreads();
        {
            const int tn = t + NS - 1;
            if (tn < NT) {
                const int kk = tn * BK;
                const uint32_t sb = sbase + (tn % NS) * STG_B;
                cp16(sb + (rA0 * ALD + cA0 * 8) * 2, A + (bm + rA0) * K + kk + cA0 * 8);
                cp16(sb + (rA1 * ALD + cA1 * 8) * 2, A + (bm + rA1) * K + kk + cA1 * 8);
                cp16(sb + 10240 + (rA0 * ALD + cA0 * 8) * 2, W + (bn + rA0) * K + kk + cA0 * 8);
                cp16(sb + 10240 + (rA1 * ALD + cA1 * 8) * 2, W + (bn + rA1) * K + kk + cA1 * 8);
            }
            asm volatile("cp.async.commit_group;");
        }
    }

    float* smf = (float*)smem;
#pragma unroll
    for (int i = 0; i < 4; i++)
#pragma unroll
        for (int j = 0; j < 2; j++)
            wmma::store_matrix_sync(smf + (wm * 64 + i * 16) * CLD + wn * 32 + j * 16,
                                    acc[i][j], CLD, wmma::mem_row_major);
    __syncthreads();

    if (mode == 2) {
        float4 gv = *(const float4*)(gamma + lane * 4);
        float4 bv = *(const float4*)(beta  + lane * 4);
        float4 bz = *(const float4*)(bias  + lane * 4);
#pragma unroll
        for (int i = 0; i < 16; i++) {
            const int row = wid * 16 + i;
            float4 v = *(float4*)(smf + row * CLD + lane * 4);
            const size_t off = (bm + row) * DD + lane * 4;
            // residual from fp16 mirror
            uint2 ru = *(const uint2*)(Xh + off);
            float2 r0 = __half22float2(*(const __half2*)&ru.x);
            float2 r1 = __half22float2(*(const __half2*)&ru.y);
            float4 tv;
            tv.x = v.x + bz.x + r0.x; tv.y = v.y + bz.y + r0.y;
            tv.z = v.z + bz.z + r1.x; tv.w = v.w + bz.w + r1.y;
            float s  = tv.x + tv.y + tv.z + tv.w;
            float s2 = tv.x*tv.x + tv.y*tv.y + tv.z*tv.z + tv.w*tv.w;
#pragma unroll
            for (int o = 16; o > 0; o >>= 1) {
                s  += __shfl_xor_sync(0xffffffffu, s,  o);
                s2 += __shfl_xor_sync(0xffffffffu, s2, o);
            }
            float mean = s * (1.f / DD);
            float var  = s2 * (1.f / DD) - mean * mean;
            float rstd = rsqrtf(var + 1e-5f);
            float4 y;
            y.x = (tv.x - mean) * rstd * gv.x + bv.x;
            y.y = (tv.y - mean) * rstd * gv.y + bv.y;
            y.z = (tv.z - mean) * rstd * gv.z + bv.z;
            y.w = (tv.w - mean) * rstd * gv.w + bv.w;
            if (wx) *(float4*)(X + off) = y;
            __half2 h0 = __floats2half2_rn(y.x, y.y);
            __half2 h1 = __floats2half2_rn(y.z, y.w);
            uint2 u;
            u.x = *reinterpret_cast<uint32_t*>(&h0);
            u.y = *reinterpret_cast<uint32_t*>(&h1);
            *(uint2*)(Xh + off) = u;
        }
    } else {
#pragma unroll
        for (int i = 0; i < 16; i++) {
            int idx = i * 256 + tid;
            int row = idx >> 5;
            int cc  = (idx & 31) * 4;
            float4 v  = *(float4*)(smf + row * CLD + cc);
            float4 bz = *(const float4*)(bias + bn + cc);
            v.x += bz.x; v.y += bz.y; v.z += bz.z; v.w += bz.w;
            __half2 h0 = __floats2half2_rn(v.x, v.y);
            __half2 h1 = __floats2half2_rn(v.z, v.w);
            uint2 u;
            u.x = *reinterpret_cast<uint32_t*>(&h0);
            u.y = *reinterpret_cast<uint32_t*>(&h1);
            *(uint2*)(Ch + (bm + row) * N + bn + cc) = u;
        }
    }
}

// ---------------------------------------------------------------------------
// attn_tc: one block per (b,h), 256 threads / 8 warps, 2 CTA/SM.
// ---------------------------------------------------------------------------
#define QLD 24
#define SLD 68
#define PLD 136
#define OLD 20
#define ATT_SMEM 89088

__global__ __launch_bounds__(256, 2) void attn_tc(
    const __half* __restrict__ qkv, const float* __restrict__ mask,
    __half* __restrict__ out)
{
    extern __shared__ __align__(16) char asmem[];
    __half* Qs = (__half*)(asmem);
    __half* Ks = (__half*)(asmem + 6144);
    __half* Vs = (__half*)(asmem + 12288);
    float*  ms = (float*) (asmem + 18432);
    float*  rs = (float*) (asmem + 18944);
    float*  Ss = (float*) (asmem + 19456);
    __half* Ps = (__half*)(asmem + 54272);
    float*  Os = (float*) (asmem);

    const int h = blockIdx.x & 7;
    const int b = blockIdx.x >> 3;
    const int tid = threadIdx.x, wid = tid >> 5;

    {
        const int row = tid >> 1, ch = tid & 1;
        const __half* base = qkv + ((size_t)b * TT + row) * (3 * DD) + h * HDIM + ch * 8;
        *(uint4*)(Qs + row * QLD + ch * 8) = *(const uint4*)(base);
        *(uint4*)(Ks + row * QLD + ch * 8) = *(const uint4*)(base + DD);
        *(uint4*)(Vs + row * QLD + ch * 8) = *(const uint4*)(base + 2 * DD);
        if (tid < TT) ms[tid] = mask[b * TT + tid];
    }
    __syncthreads();

    wmma::fragment<wmma::matrix_a, 16, 16, 16, __half, wmma::row_major> qf;
    wmma::load_matrix_sync(qf, Qs + wid * 16 * QLD, QLD);

    float sum = 0.f;
    const int er = tid >> 1;
    const int eh = tid & 1;

    for (int chunk = 0; chunk < 2; chunk++) {
#pragma unroll
        for (int j = 0; j < 4; j++) {
            wmma::fragment<wmma::matrix_b, 16, 16, 16, __half, wmma::col_major> kf;
            wmma::fragment<wmma::accumulator, 16, 16, 16, float> sf;
            wmma::load_matrix_sync(kf, Ks + (chunk * 64 + j * 16) * QLD, QLD);
            wmma::fill_fragment(sf, 0.f);
            wmma::mma_sync(sf, qf, kf, sf);
            wmma::store_matrix_sync(Ss + (wid * 16) * SLD + j * 16, sf, SLD, wmma::mem_row_major);
        }
        __syncthreads();
        {
            const float* srow = Ss + er * SLD + eh * 32;
            __half* prow = Ps + er * PLD + chunk * 64 + eh * 32;
            const float* mrow = ms + chunk * 64 + eh * 32;
#pragma unroll
            for (int c = 0; c < 32; c++) {
                float p = fast_exp_s6(fmaf(srow[c], 0.25f, mrow[c]));
                __half ph = __float2half_rn(p);
                prow[c] = ph;
                sum += __half2float(ph);
            }
        }
        __syncthreads();
    }
    sum += __shfl_xor_sync(0xffffffffu, sum, 1);
    if (!eh) rs[er] = sum;
    __syncthreads();

    {
        wmma::fragment<wmma::accumulator, 16, 16, 16, float> of;
        wmma::fill_fragment(of, 0.f);
#pragma unroll
        for (int j = 0; j < 8; j++) {
            wmma::fragment<wmma::matrix_a, 16, 16, 16, __half, wmma::row_major> pf;
            wmma::fragment<wmma::matrix_b, 16, 16, 16, __half, wmma::row_major> vf;
            wmma::load_matrix_sync(pf, Ps + (wid * 16) * PLD + j * 16, PLD);
            wmma::load_matrix_sync(vf, Vs + (j * 16) * QLD, QLD);
            wmma::mma_sync(of, pf, vf, of);
        }
        wmma::store_matrix_sync(Os + (wid * 16) * OLD, of, OLD, wmma::mem_row_major);
    }
    __syncthreads();

    {
        const int r = tid >> 1, c0 = (tid & 1) * 8;
        const float inv = 1.f / rs[r];
        const float* orow = Os + r * OLD + c0;
        uint4 u;
        uint32_t* pu = &u.x;
#pragma unroll
        for (int j = 0; j < 4; j++) {
            __half2 hv = __floats2half2_rn(orow[j * 2] * inv, orow[j * 2 + 1] * inv);
            pu[j] = *reinterpret_cast<uint32_t*>(&hv);
        }
        *(uint4*)(out + ((size_t)b * TT + r) * DD + h * HDIM + c0) = u;
    }
}

// ===========================================================================
// ff_fused: X <- LN(Xh + relu(x@W1^T+b1)@W2^T + b2); residual from smem Xs.
// ===========================================================================
#define A_LD    136
#define A_WLD   40
#define F_XS    0
#define F_STG   34816
#define F_HC    69632
#define F_WBUF  88064
#define F_SMEM  108544
#define F_HLD   72

__global__ __launch_bounds__(256, 2) void ff_fused(
    const __half* __restrict__ xh, const __half* __restrict__ w1,
    const float* __restrict__ b1, const __half* __restrict__ w2,
    const float* __restrict__ b2,
    float* __restrict__ X, __half* __restrict__ Xh,
    const float* __restrict__ gamma, const float* __restrict__ beta, int wx)
{
    extern __shared__ __align__(16) char sm[];
    const uint32_t sb = smem_u32(sm);
    const int tid  = threadIdx.x;
    const int wid  = tid >> 5;
    const int lane = tid & 31;
    const size_t bm = (size_t)blockIdx.x * 128;

    const int wm1 = wid & 3, wn1 = wid >> 2;
    const int wm2 = wid & 1, wn2 = wid >> 1;

    const int r1 = tid >> 2, c4 = tid & 3;
    const uint32_t wdst0 = (r1 * A_WLD + c4 * 8) * 2;
    const uint32_t wdst1 = ((r1 + 64) * A_WLD + c4 * 8) * 2;
    const __half* w1p = w1 + (size_t)r1 * DD + c4 * 8;
    const __half* w2p0 = w2 + (size_t)r1 * FFD + c4 * 8;
    const __half* w2p1 = w2 + (size_t)(r1 + 64) * FFD + c4 * 8;

    {
#pragma unroll
        for (int p = 0; p < 8; p++) {
            int id = p * 256 + tid;
            int row = id >> 4, c = id & 15;
            cp16(sb + F_XS + row * (A_LD * 2) + c * 16, xh + (bm + row) * DD + c * 8);
        }
        asm volatile("cp.async.commit_group;");
    }
    cp16(sb + F_WBUF + wdst0, w1p);
    asm volatile("cp.async.commit_group;");

    wmma::fragment<wmma::accumulator, 16, 16, 16, float> acc[4][2];
#pragma unroll
    for (int i = 0; i < 4; i++)
#pragma unroll
        for (int jj = 0; jj < 2; jj++) wmma::fill_fragment(acc[i][jj], 0.f);
    wmma::fragment<wmma::accumulator, 16, 16, 16, float> acc1[2][2];

    const __half* Xs = (const __half*)(sm + F_XS);
    float* stg = (float*)(sm + F_STG);
    __half* hc = (__half*)(sm + F_HC);

    int cn = 0, phn = 0;
    for (int j = 0; j < 48; j++) {
        const int c = cn, ph = phn;
        if (j < 47) {
            if (++phn == 6) { phn = 0; cn++; }
            const uint32_t wb = sb + F_WBUF + ((j + 1) & 1) * 10240;
            if (phn < 4) {
                cp16(wb + wdst0, w1p + (size_t)cn * 64 * DD + phn * 32);
            } else {
                const int t2 = phn - 4;
                cp16(wb + wdst0, w2p0 + cn * 64 + t2 * 32);
                cp16(wb + wdst1, w2p1 + cn * 64 + t2 * 32);
            }
            asm volatile("cp.async.commit_group;");
            asm volatile("cp.async.wait_group 1;");
        } else {
            asm volatile("cp.async.wait_group 0;");
        }
        __syncthreads();

        const __half* Wb = (const __half*)(sm + F_WBUF + (j & 1) * 10240);
        if (ph < 4) {
            if (ph == 0) {
#pragma unroll
                for (int i = 0; i < 2; i++)
#pragma unroll
                    for (int jj = 0; jj < 2; jj++) wmma::fill_fragment(acc1[i][jj], 0.f);
            }
#pragma unroll
            for (int ks = 0; ks < 2; ks++) {
                wmma::fragment<wmma::matrix_a, 16, 16, 16, __half, wmma::row_major> af[2];
                wmma::fragment<wmma::matrix_b, 16, 16, 16, __half, wmma::col_major> bf[2];
#pragma unroll
                for (int i = 0; i < 2; i++)
                    wmma::load_matrix_sync(af[i], Xs + (wm1 * 32 + i * 16) * A_LD + ph * 32 + ks * 16, A_LD);
#pragma unroll
                for (int jj = 0; jj < 2; jj++)
                    wmma::load_matrix_sync(bf[jj], Wb + (wn1 * 32 + jj * 16) * A_WLD + ks * 16, A_WLD);
#pragma unroll
                for (int i = 0; i < 2; i++)
#pragma unroll
                    for (int jj = 0; jj < 2; jj++)
                        wmma::mma_sync(acc1[i][jj], af[i], bf[jj], acc1[i][jj]);
            }
            if (ph == 3) {
#pragma unroll
                for (int i = 0; i < 2; i++)
#pragma unroll
                    for (int jj = 0; jj < 2; jj++)
                        wmma::store_matrix_sync(stg + (wm1 * 32 + i * 16) * 68 + wn1 * 32 + jj * 16,
                                                acc1[i][jj], 68, wmma::mem_row_major);
                __syncthreads();
                const float* bc = b1 + c * 64;
#pragma unroll
                for (int q = 0; q < 16; q++) {
                    int id = q * 256 + tid;
                    int row = id >> 5, col = (id & 31) * 2;
                    float v0 = fmaxf(stg[row * 68 + col]     + bc[col],     0.f);
                    float v1 = fmaxf(stg[row * 68 + col + 1] + bc[col + 1], 0.f);
                    *(__half2*)(hc + row * F_HLD + col) = __floats2half2_rn(v0, v1);
                }
            }
        } else {
            const int t2 = ph - 4;
#pragma unroll
            for (int ks = 0; ks < 2; ks++) {
                wmma::fragment<wmma::matrix_a, 16, 16, 16, __half, wmma::row_major> af[4];
                wmma::fragment<wmma::matrix_b, 16, 16, 16, __half, wmma::col_major> bf[2];
#pragma unroll
                for (int i = 0; i < 4; i++)
                    wmma::load_matrix_sync(af[i], hc + (wm2 * 64 + i * 16) * F_HLD + t2 * 32 + ks * 16, F_HLD);
#pragma unroll
                for (int jj = 0; jj < 2; jj++)
                    wmma::load_matrix_sync(bf[jj], Wb + (wn2 * 32 + jj * 16) * A_WLD + ks * 16, A_WLD);
#pragma unroll
                for (int i = 0; i < 4; i++)
#pragma unroll
                    for (int jj = 0; jj < 2; jj++)
                        wmma::mma_sync(acc[i][jj], af[i], bf[jj], acc[i][jj]);
            }
        }
        __syncthreads();
    }

    // epilogue: residual (from smem Xs, fp16) + LN (2 passes of 64 rows)
    float* s64 = (float*)(sm + F_STG);
    float4 gv = *(const float4*)(gamma + lane * 4);
    float4 bv = *(const float4*)(beta  + lane * 4);
    float4 bz = *(const float4*)(b2    + lane * 4);
#pragma unroll
    for (int pass = 0; pass < 2; pass++) {
        if (wm2 == pass) {
#pragma unroll
            for (int i = 0; i < 4; i++)
#pragma unroll
                for (int jj = 0; jj < 2; jj++)
                    wmma::store_matrix_sync(s64 + (i * 16) * 132 + wn2 * 32 + jj * 16,
                                            acc[i][jj], 132, wmma::mem_row_major);
        }
        __syncthreads();
#pragma unroll
        for (int rr = 0; rr < 8; rr++) {
            const int r64 = wid * 8 + rr;
            const int rloc = pass * 64 + r64;
            float4 v = *(float4*)(s64 + r64 * 132 + lane * 4);
            const size_t off = (bm + rloc) * DD + lane * 4;
            uint2 ru = *(const uint2*)(Xs + rloc * A_LD + lane * 4);
            float2 x0 = __half22float2(*(const __half2*)&ru.x);
            float2 x1 = __half22float2(*(const __half2*)&ru.y);
            float4 tv;
            tv.x = v.x + bz.x + x0.x; tv.y = v.y + bz.y + x0.y;
            tv.z = v.z + bz.z + x1.x; tv.w = v.w + bz.w + x1.y;
            float s  = tv.x + tv.y + tv.z + tv.w;
            float s2 = tv.x*tv.x + tv.y*tv.y + tv.z*tv.z + tv.w*tv.w;
#pragma unroll
            for (int o = 16; o > 0; o >>= 1) {
                s  += __shfl_xor_sync(0xffffffffu, s,  o);
                s2 += __shfl_xor_sync(0xffffffffu, s2, o);
            }
            float mean = s * (1.f / DD);
            float var  = s2 * (1.f / DD) - mean * mean;
            float rstd = rsqrtf(var + 1e-5f);
            float4 y;
            y.x = (tv.x - mean) * rstd * gv.x + bv.x;
            y.y = (tv.y - mean) * rstd * gv.y + bv.y;
            y.z = (tv.z - mean) * rstd * gv.z + bv.z;
            y.w = (tv.w - mean) * rstd * gv.w + bv.w;
            if (wx) *(float4*)(X + off) = y;
            __half2 h0 = __floats2half2_rn(y.x, y.y);
            __half2 h1 = __floats2half2_rn(y.z, y.w);
            uint2 u;
            u.x = *reinterpret_cast<uint32_t*>(&h0);
            u.y = *reinterpret_cast<uint32_t*>(&h1);
            *(uint2*)(Xh + off) = u;
        }
        __syncthreads();
    }
}

// ---------------------------------------------------------------------------
extern "C" void kernel_launch(void* const* d_in, const int* in_sizes, int n_in,
                              void* d_out, int out_size)
{
    const float* x_in      = (const float*)d_in[0];
    const float* mask      = (const float*)d_in[1];
    const float* in_proj_w = (const float*)d_in[2];
    const float* in_proj_b = (const float*)d_in[3];
    const float* out_w     = (const float*)d_in[4];
    const float* out_b     = (const float*)d_in[5];
    const float* ln1_g     = (const float*)d_in[6];
    const float* ln1_b     = (const float*)d_in[7];
    const float* ff1_w     = (const float*)d_in[8];
    const float* ff1_b     = (const float*)d_in[9];
    const float* ff2_w     = (const float*)d_in[10];
    const float* ff2_b     = (const float*)d_in[11];
    const float* ln2_g     = (const float*)d_in[12];
    const float* ln2_b     = (const float*)d_in[13];
    float* x = (float*)d_out;

    __half *wqkv, *wout, *wff1, *wff2, *xh, *qkvh, *attnh;
    cudaGetSymbolAddress((void**)&wqkv, g_wqkv);
    cudaGetSymbolAddress((void**)&wout, g_wout);
    cudaGetSymbolAddress((void**)&wff1, g_wff1);
    cudaGetSymbolAddress((void**)&wff2, g_wff2);
    cudaGetSymbolAddress((void**)&xh,   g_xh);
    cudaGetSymbolAddress((void**)&qkvh, g_qkvh);
    cudaGetSymbolAddress((void**)&attnh,g_attnh);

    cudaFuncSetAttribute(gemm_h,   cudaFuncAttributeMaxDynamicSharedMemorySize, SMEM_DYN);
    cudaFuncSetAttribute(attn_tc,  cudaFuncAttributeMaxDynamicSharedMemorySize, ATT_SMEM);
    cudaFuncSetAttribute(ff_fused, cudaFuncAttributeMaxDynamicSharedMemorySize, F_SMEM);

    cvt_all<<<(N_CVT + 255) / 256, 256>>>(x_in, in_proj_w, out_w, ff1_w, ff2_w);

    for (int l = 0; l < NL; l++) {
        gemm_h<<<dim3(3, MM / 128), 256, SMEM_DYN>>>(
            xh, wqkv + (size_t)l * 3 * DD * DD, in_proj_b + (size_t)l * 3 * DD,
            qkvh, nullptr, nullptr, nullptr, nullptr, 3 * DD, DD, 0, 0);
        attn_tc<<<BB * HH, 256, ATT_SMEM>>>(qkvh, mask, attnh);
        gemm_h<<<dim3(1, MM / 128), 256, SMEM_DYN>>>(
            attnh, wout + (size_t)l * DD * DD, out_b + (size_t)l * DD,
            nullptr, x, xh, ln1_g + (size_t)l * DD, ln1_b + (size_t)l * DD, DD, DD, 2, 0);
        ff_fused<<<MM / 128, 256, F_SMEM>>>(
            xh, wff1 + (size_t)l * FFD * DD, ff1_b + (size_t)l * FFD,
            wff2 + (size_t)l * DD * FFD, ff2_b + (size_t)l * DD,
            x, xh, ln2_g + (size_t)l * DD, ln2_b + (size_t)l * DD,
            (l == NL - 1) ? 1 : 0);
    }
}

// round 15
// speedup vs baseline: 1.6729x; 1.0491x over previous
#include <cuda_runtime.h>
#include <cuda_fp16.h>
#include <mma.h>
#include <cstdint>
using namespace nvcuda;

// Problem dims (fixed)
#define BB   1024
#define TT   128
#define DD   128
#define HH   8
#define HDIM 16
#define FFD  512
#define NL   2
#define MM   (BB*TT)          // 131072 tokens

// fp16 scratch
__device__ __half g_wqkv[(size_t)NL * 3 * DD * DD];
__device__ __half g_wout[(size_t)NL * DD * DD];
__device__ __half g_wff1[(size_t)NL * FFD * DD];
__device__ __half g_wff2[(size_t)NL * DD * FFD];
__device__ __half g_xh  [(size_t)MM * DD];
__device__ __half g_qkvh[(size_t)MM * 3 * DD];
__device__ __half g_attnh[(size_t)MM * DD];

// ---------------------------------------------------------------------------
#define N_XH4 (MM * DD / 4)
#define N_WQ4 (NL * 3 * DD * DD / 4)
#define N_WO4 (NL * DD * DD / 4)
#define N_W14 (NL * FFD * DD / 4)
#define N_W24 (NL * DD * FFD / 4)
#define N_CVT (N_XH4 + N_WQ4 + N_WO4 + N_W14 + N_W24)

__global__ void cvt_all(const float* __restrict__ x,
                        const float* __restrict__ wq,
                        const float* __restrict__ wo,
                        const float* __restrict__ w1,
                        const float* __restrict__ w2)
{
    long i = (long)blockIdx.x * blockDim.x + threadIdx.x;
    if (i >= N_CVT) return;
    const float* src;
    __half* dst;
    long off = i;
    if (off < N_XH4)                      { src = x;  dst = g_xh;   }
    else if ((off -= N_XH4) < N_WQ4)      { src = wq; dst = g_wqkv; }
    else if ((off -= N_WQ4) < N_WO4)      { src = wo; dst = g_wout; }
    else if ((off -= N_WO4) < N_W14)      { src = w1; dst = g_wff1; }
    else  { off -= N_W14;                   src = w2; dst = g_wff2; }
    float4 v = ((const float4*)src)[off];
    __half2 h0 = __floats2half2_rn(v.x, v.y);
    __half2 h1 = __floats2half2_rn(v.z, v.w);
    uint2 u;
    u.x = *reinterpret_cast<uint32_t*>(&h0);
    u.y = *reinterpret_cast<uint32_t*>(&h1);
    ((uint2*)dst)[off] = u;
}

__device__ __forceinline__ uint32_t smem_u32(const void* p) {
    uint32_t a;
    asm("{ .reg .u64 t; cvta.to.shared.u64 t, %1; cvt.u32.u64 %0, t; }"
        : "=r"(a) : "l"(p));
    return a;
}
__device__ __forceinline__ void cp16(uint32_t dst, const void* src) {
    asm volatile("cp.async.ca.shared.global [%0], [%1], 16;" :: "r"(dst), "l"(src));
}
__device__ __forceinline__ float fast_exp_s6(float x) {
    x = fmaxf(x, -80.f);
    float t  = x * 1.4426950408889634f;
    float fn = t + 12582912.f;
    int   ni = __float_as_int(fn) - 0x4B400000;
    float r  = t - (fn - 12582912.f);
    float p  = 0.00133336f;
    p = fmaf(p, r, 0.00961813f);
    p = fmaf(p, r, 0.05550411f);
    p = fmaf(p, r, 0.24022651f);
    p = fmaf(p, r, 0.69314718f);
    p = fmaf(p, r, 1.0f);
    return p * __int_as_float((ni + 121) << 23);   // * 2^(n-6)
}

// ---------------------------------------------------------------------------
// gemm_h: qkv projection (mode 0), fp16 out.
// ---------------------------------------------------------------------------
#define BK   32
#define ALD  40
#define STG_B 20480
#define NS   4
#define CLD  132
#define SMEM_DYN (NS*STG_B)

__global__ __launch_bounds__(256, 2) void gemm_h(
    const __half* __restrict__ A, const __half* __restrict__ W,
    const float* __restrict__ bias, __half* __restrict__ Ch,
    int N, int K)
{
    extern __shared__ __align__(16) char smem[];
    const uint32_t sbase = smem_u32(smem);
    const int tid  = threadIdx.x;
    const int wid  = tid >> 5;
    const int wm   = wid & 1;
    const int wn   = wid >> 1;
    const size_t bm = (size_t)blockIdx.y * 128;
    const size_t bn = (size_t)blockIdx.x * 128;
    const int NT = K / BK;

    const int rA0 = tid >> 2, cA0 = tid & 3;
    const int rA1 = (tid + 256) >> 2, cA1 = (tid + 256) & 3;

    wmma::fragment<wmma::accumulator, 16, 16, 16, float> acc[4][2];
#pragma unroll
    for (int i = 0; i < 4; i++)
#pragma unroll
        for (int j = 0; j < 2; j++) wmma::fill_fragment(acc[i][j], 0.f);

#pragma unroll
    for (int t = 0; t < NS - 1; t++) {
        if (t < NT) {
            const int kk = t * BK;
            const uint32_t sb = sbase + (t % NS) * STG_B;
            cp16(sb + (rA0 * ALD + cA0 * 8) * 2, A + (bm + rA0) * K + kk + cA0 * 8);
            cp16(sb + (rA1 * ALD + cA1 * 8) * 2, A + (bm + rA1) * K + kk + cA1 * 8);
            cp16(sb + 10240 + (rA0 * ALD + cA0 * 8) * 2, W + (bn + rA0) * K + kk + cA0 * 8);
            cp16(sb + 10240 + (rA1 * ALD + cA1 * 8) * 2, W + (bn + rA1) * K + kk + cA1 * 8);
        }
        asm volatile("cp.async.commit_group;");
    }

    for (int t = 0; t < NT; t++) {
        asm volatile("cp.async.wait_group %0;" :: "n"(NS - 2));
        __syncthreads();
        {
            const __half* As = (const __half*)(smem + (t % NS) * STG_B);
            const __half* Ws = As + 5120;
#pragma unroll
            for (int ks = 0; ks < 2; ks++) {
                wmma::fragment<wmma::matrix_a, 16, 16, 16, __half, wmma::row_major> af[4];
                wmma::fragment<wmma::matrix_b, 16, 16, 16, __half, wmma::col_major> bf[2];
#pragma unroll
                for (int i = 0; i < 4; i++)
                    wmma::load_matrix_sync(af[i], As + (wm * 64 + i * 16) * ALD + ks * 16, ALD);
#pragma unroll
                for (int j = 0; j < 2; j++)
                    wmma::load_matrix_sync(bf[j], Ws + (wn * 32 + j * 16) * ALD + ks * 16, ALD);
#pragma unroll
                for (int i = 0; i < 4; i++)
#pragma unroll
                    for (int j = 0; j < 2; j++)
                        wmma::mma_sync(acc[i][j], af[i], bf[j], acc[i][j]);
            }
        }
        __syncthreads();
        {
            const int tn = t + NS - 1;
            if (tn < NT) {
                const int kk = tn * BK;
                const uint32_t sb = sbase + (tn % NS) * STG_B;
                cp16(sb + (rA0 * ALD + cA0 * 8) * 2, A + (bm + rA0) * K + kk + cA0 * 8);
                cp16(sb + (rA1 * ALD + cA1 * 8) * 2, A + (bm + rA1) * K + kk + cA1 * 8);
                cp16(sb + 10240 + (rA0 * ALD + cA0 * 8) * 2, W + (bn + rA0) * K + kk + cA0 * 8);
                cp16(sb + 10240 + (rA1 * ALD + cA1 * 8) * 2, W + (bn + rA1) * K + kk + cA1 * 8);
            }
            asm volatile("cp.async.commit_group;");
        }
    }

    float* smf = (float*)smem;
#pragma unroll
    for (int i = 0; i < 4; i++)
#pragma unroll
        for (int j = 0; j < 2; j++)
            wmma::store_matrix_sync(smf + (wm * 64 + i * 16) * CLD + wn * 32 + j * 16,
                                    acc[i][j], CLD, wmma::mem_row_major);
    __syncthreads();

#pragma unroll
    for (int i = 0; i < 16; i++) {
        int idx = i * 256 + tid;
        int row = idx >> 5;
        int cc  = (idx & 31) * 4;
        float4 v  = *(float4*)(smf + row * CLD + cc);
        float4 bz = *(const float4*)(bias + bn + cc);
        v.x += bz.x; v.y += bz.y; v.z += bz.z; v.w += bz.w;
        __half2 h0 = __floats2half2_rn(v.x, v.y);
        __half2 h1 = __floats2half2_rn(v.z, v.w);
        uint2 u;
        u.x = *reinterpret_cast<uint32_t*>(&h0);
        u.y = *reinterpret_cast<uint32_t*>(&h1);
        *(uint2*)(Ch + (bm + row) * N + bn + cc) = u;
    }
}

// ---------------------------------------------------------------------------
// attn_tc: one block per (b,h), 256 threads / 8 warps, 2 CTA/SM.
// ---------------------------------------------------------------------------
#define QLD 24
#define SLD 68
#define PLD 136
#define OLD 20
#define ATT_SMEM 89088

__global__ __launch_bounds__(256, 2) void attn_tc(
    const __half* __restrict__ qkv, const float* __restrict__ mask,
    __half* __restrict__ out)
{
    extern __shared__ __align__(16) char asmem[];
    __half* Qs = (__half*)(asmem);
    __half* Ks = (__half*)(asmem + 6144);
    __half* Vs = (__half*)(asmem + 12288);
    float*  ms = (float*) (asmem + 18432);
    float*  rs = (float*) (asmem + 18944);
    float*  Ss = (float*) (asmem + 19456);
    __half* Ps = (__half*)(asmem + 54272);
    float*  Os = (float*) (asmem);

    const int h = blockIdx.x & 7;
    const int b = blockIdx.x >> 3;
    const int tid = threadIdx.x, wid = tid >> 5;

    {
        const int row = tid >> 1, ch = tid & 1;
        const __half* base = qkv + ((size_t)b * TT + row) * (3 * DD) + h * HDIM + ch * 8;
        *(uint4*)(Qs + row * QLD + ch * 8) = *(const uint4*)(base);
        *(uint4*)(Ks + row * QLD + ch * 8) = *(const uint4*)(base + DD);
        *(uint4*)(Vs + row * QLD + ch * 8) = *(const uint4*)(base + 2 * DD);
        if (tid < TT) ms[tid] = mask[b * TT + tid];
    }
    __syncthreads();

    wmma::fragment<wmma::matrix_a, 16, 16, 16, __half, wmma::row_major> qf;
    wmma::load_matrix_sync(qf, Qs + wid * 16 * QLD, QLD);

    float sum = 0.f;
    const int er = tid >> 1;
    const int eh = tid & 1;

    for (int chunk = 0; chunk < 2; chunk++) {
#pragma unroll
        for (int j = 0; j < 4; j++) {
            wmma::fragment<wmma::matrix_b, 16, 16, 16, __half, wmma::col_major> kf;
            wmma::fragment<wmma::accumulator, 16, 16, 16, float> sf;
            wmma::load_matrix_sync(kf, Ks + (chunk * 64 + j * 16) * QLD, QLD);
            wmma::fill_fragment(sf, 0.f);
            wmma::mma_sync(sf, qf, kf, sf);
            wmma::store_matrix_sync(Ss + (wid * 16) * SLD + j * 16, sf, SLD, wmma::mem_row_major);
        }
        __syncthreads();
        {
            const float* srow = Ss + er * SLD + eh * 32;
            __half* prow = Ps + er * PLD + chunk * 64 + eh * 32;
            const float* mrow = ms + chunk * 64 + eh * 32;
#pragma unroll
            for (int c = 0; c < 32; c++) {
                float p = fast_exp_s6(fmaf(srow[c], 0.25f, mrow[c]));
                __half ph = __float2half_rn(p);
                prow[c] = ph;
                sum += __half2float(ph);
            }
        }
        __syncthreads();
    }
    sum += __shfl_xor_sync(0xffffffffu, sum, 1);
    if (!eh) rs[er] = sum;
    __syncthreads();

    {
        wmma::fragment<wmma::accumulator, 16, 16, 16, float> of;
        wmma::fill_fragment(of, 0.f);
#pragma unroll
        for (int j = 0; j < 8; j++) {
            wmma::fragment<wmma::matrix_a, 16, 16, 16, __half, wmma::row_major> pf;
            wmma::fragment<wmma::matrix_b, 16, 16, 16, __half, wmma::row_major> vf;
            wmma::load_matrix_sync(pf, Ps + (wid * 16) * PLD + j * 16, PLD);
            wmma::load_matrix_sync(vf, Vs + (j * 16) * QLD, QLD);
            wmma::mma_sync(of, pf, vf, of);
        }
        wmma::store_matrix_sync(Os + (wid * 16) * OLD, of, OLD, wmma::mem_row_major);
    }
    __syncthreads();

    {
        const int r = tid >> 1, c0 = (tid & 1) * 8;
        const float inv = 1.f / rs[r];
        const float* orow = Os + r * OLD + c0;
        uint4 u;
        uint32_t* pu = &u.x;
#pragma unroll
        for (int j = 0; j < 4; j++) {
            __half2 hv = __floats2half2_rn(orow[j * 2] * inv, orow[j * 2 + 1] * inv);
            pu[j] = *reinterpret_cast<uint32_t*>(&hv);
        }
        *(uint4*)(out + ((size_t)b * TT + r) * DD + h * HDIM + c0) = u;
    }
}

// ===========================================================================
// of_fused: per 128-token tile:
//   x1 = LN1(xh + attnh @ Wo^T + bo)                 (stays in smem)
//   Xh = LN2(x1 + relu(x1@W1^T+b1) @ W2^T + b2)      (+ X fp32 on last layer)
// smem: R0[0,34816) = attnh tile / staging; R1 = residual / x1;
//       HC = relu'd h chunk; WB = 2-deep weight ring.  2 CTA/SM.
// ===========================================================================
#define A_LD    136
#define A_WLD   40
#define R1_OFF  34816
#define HC_OFF  69632
#define WB_OFF  88064
#define F_SMEM  108544
#define F_HLD   72

__global__ __launch_bounds__(256, 2) void of_fused(
    const __half* __restrict__ attnh, const __half* __restrict__ wo,
    const float* __restrict__ bo,
    const float* __restrict__ g1, const float* __restrict__ be1,
    const __half* __restrict__ w1, const float* __restrict__ b1,
    const __half* __restrict__ w2, const float* __restrict__ b2,
    const float* __restrict__ g2, const float* __restrict__ be2,
    __half* __restrict__ Xh, float* __restrict__ X, int wx)
{
    extern __shared__ __align__(16) char sm[];
    const uint32_t sb = smem_u32(sm);
    const int tid  = threadIdx.x;
    const int wid  = tid >> 5;
    const int lane = tid & 31;
    const size_t bm = (size_t)blockIdx.x * 128;

    const int wm1 = wid & 3, wn1 = wid >> 2;   // FF1: 4x2 warps, 32x32
    const int wm2 = wid & 1, wn2 = wid >> 1;   // outproj/FF2: 2x4 warps, 64x32

    // per-thread cp.async state
    const int r1 = tid >> 2, c4 = tid & 3;
    const uint32_t wdst0 = (r1 * A_WLD + c4 * 8) * 2;
    const uint32_t wdst1 = ((r1 + 64) * A_WLD + c4 * 8) * 2;
    const __half* wop0 = wo + (size_t)r1 * DD + c4 * 8;
    const __half* wop1 = wo + (size_t)(r1 + 64) * DD + c4 * 8;
    const __half* w1p  = w1 + (size_t)r1 * DD + c4 * 8;
    const __half* w2p0 = w2 + (size_t)r1 * FFD + c4 * 8;
    const __half* w2p1 = w2 + (size_t)(r1 + 64) * FFD + c4 * 8;

    // prologue: attnh tile (R0) + residual xh tile (R1), then Wo tile 0
    {
#pragma unroll
        for (int p = 0; p < 8; p++) {
            int id = p * 256 + tid;
            int row = id >> 4, c = id & 15;
            cp16(sb + row * (A_LD * 2) + c * 16, attnh + (bm + row) * DD + c * 8);
            cp16(sb + R1_OFF + row * (A_LD * 2) + c * 16, Xh + (bm + row) * DD + c * 8);
        }
        asm volatile("cp.async.commit_group;");
    }
    cp16(sb + WB_OFF + wdst0, wop0);
    cp16(sb + WB_OFF + wdst1, wop1);
    asm volatile("cp.async.commit_group;");

    const __half* As  = (const __half*)sm;            // attnh tile
    __half* x1 = (__half*)(sm + R1_OFF);              // residual -> LN1 out
    float* stg = (float*)sm;                          // staging (aliases As)
    __half* hc = (__half*)(sm + HC_OFF);

    // ---- loop A: out-proj (4 phases) ----
    {
        wmma::fragment<wmma::accumulator, 16, 16, 16, float> aop[4][2];
#pragma unroll
        for (int i = 0; i < 4; i++)
#pragma unroll
            for (int jj = 0; jj < 2; jj++) wmma::fill_fragment(aop[i][jj], 0.f);

#pragma unroll
        for (int j = 0; j < 4; j++) {
            // issue next: Wo tile j+1, or FF tile 0 (W1 c=0 ph=0) at j==3
            {
                const uint32_t wb = sb + WB_OFF + ((j + 1) & 1) * 10240;
                if (j < 3) {
                    cp16(wb + wdst0, wop0 + (j + 1) * 32);
                    cp16(wb + wdst1, wop1 + (j + 1) * 32);
                } else {
                    cp16(wb + wdst0, w1p);
                }
                asm volatile("cp.async.commit_group;");
            }
            asm volatile("cp.async.wait_group 1;");
            __syncthreads();
            const __half* Wb = (const __half*)(sm + WB_OFF + (j & 1) * 10240);
#pragma unroll
            for (int ks = 0; ks < 2; ks++) {
                wmma::fragment<wmma::matrix_a, 16, 16, 16, __half, wmma::row_major> af[4];
                wmma::fragment<wmma::matrix_b, 16, 16, 16, __half, wmma::col_major> bf[2];
#pragma unroll
                for (int i = 0; i < 4; i++)
                    wmma::load_matrix_sync(af[i], As + (wm2 * 64 + i * 16) * A_LD + j * 32 + ks * 16, A_LD);
#pragma unroll
                for (int jj = 0; jj < 2; jj++)
                    wmma::load_matrix_sync(bf[jj], Wb + (wn2 * 32 + jj * 16) * A_WLD + ks * 16, A_WLD);
#pragma unroll
                for (int i = 0; i < 4; i++)
#pragma unroll
                    for (int jj = 0; jj < 2; jj++)
                        wmma::mma_sync(aop[i][jj], af[i], bf[jj], aop[i][jj]);
            }
            __syncthreads();
        }

        // ---- LN1 epilogue: stage 64 rows at a time into R0, fold residual ----
        float4 gv = *(const float4*)(g1  + lane * 4);
        float4 bv = *(const float4*)(be1 + lane * 4);
        float4 bz = *(const float4*)(bo  + lane * 4);
#pragma unroll
        for (int pass = 0; pass < 2; pass++) {
            if (wm2 == pass) {
#pragma unroll
                for (int i = 0; i < 4; i++)
#pragma unroll
                    for (int jj = 0; jj < 2; jj++)
                        wmma::store_matrix_sync(stg + (i * 16) * 132 + wn2 * 32 + jj * 16,
                                                aop[i][jj], 132, wmma::mem_row_major);
            }
            __syncthreads();
#pragma unroll
            for (int rr = 0; rr < 8; rr++) {
                const int r64 = wid * 8 + rr;
                const int rloc = pass * 64 + r64;
                float4 v = *(float4*)(stg + r64 * 132 + lane * 4);
                uint2 ru = *(const uint2*)(x1 + rloc * A_LD + lane * 4);
                float2 x0 = __half22float2(*(const __half2*)&ru.x);
                float2 xx1 = __half22float2(*(const __half2*)&ru.y);
                float4 tv;
                tv.x = v.x + bz.x + x0.x; tv.y = v.y + bz.y + x0.y;
                tv.z = v.z + bz.z + xx1.x; tv.w = v.w + bz.w + xx1.y;
                float s  = tv.x + tv.y + tv.z + tv.w;
                float s2 = tv.x*tv.x + tv.y*tv.y + tv.z*tv.z + tv.w*tv.w;
#pragma unroll
                for (int o = 16; o > 0; o >>= 1) {
                    s  += __shfl_xor_sync(0xffffffffu, s,  o);
                    s2 += __shfl_xor_sync(0xffffffffu, s2, o);
                }
                float mean = s * (1.f / DD);
                float var  = s2 * (1.f / DD) - mean * mean;
                float rstd = rsqrtf(var + 1e-5f);
                float4 y;
                y.x = (tv.x - mean) * rstd * gv.x + bv.x;
                y.y = (tv.y - mean) * rstd * gv.y + bv.y;
                y.z = (tv.z - mean) * rstd * gv.z + bv.z;
                y.w = (tv.w - mean) * rstd * gv.w + bv.w;
                __half2 h0 = __floats2half2_rn(y.x, y.y);
                __half2 h1 = __floats2half2_rn(y.z, y.w);
                uint2 u;
                u.x = *reinterpret_cast<uint32_t*>(&h0);
                u.y = *reinterpret_cast<uint32_t*>(&h1);
                *(uint2*)(x1 + rloc * A_LD + lane * 4) = u;   // in-place
            }
            __syncthreads();
        }
    }

    // ---- loop B: FF (48 phases), A operand = x1 (smem) ----
    wmma::fragment<wmma::accumulator, 16, 16, 16, float> acc[4][2];
#pragma unroll
    for (int i = 0; i < 4; i++)
#pragma unroll
        for (int jj = 0; jj < 2; jj++) wmma::fill_fragment(acc[i][jj], 0.f);
    wmma::fragment<wmma::accumulator, 16, 16, 16, float> acc1[2][2];

    int cn = 0, phn = 0;   // next-issue counters (track jb+1)
    for (int jb = 0; jb < 48; jb++) {
        const int c = cn, ph = phn;
        if (jb < 47) {
            if (++phn == 6) { phn = 0; cn++; }
            const uint32_t wb = sb + WB_OFF + ((jb + 1) & 1) * 10240;
            if (phn < 4) {
                cp16(wb + wdst0, w1p + (size_t)cn * 64 * DD + phn * 32);
            } else {
                const int t2 = phn - 4;
                cp16(wb + wdst0, w2p0 + cn * 64 + t2 * 32);
                cp16(wb + wdst1, w2p1 + cn * 64 + t2 * 32);
            }
            asm volatile("cp.async.commit_group;");
            asm volatile("cp.async.wait_group 1;");
        } else {
            asm volatile("cp.async.wait_group 0;");
        }
        __syncthreads();

        const __half* Wb = (const __half*)(sm + WB_OFF + (jb & 1) * 10240);
        if (ph < 4) {
            if (ph == 0) {
#pragma unroll
                for (int i = 0; i < 2; i++)
#pragma unroll
                    for (int jj = 0; jj < 2; jj++) wmma::fill_fragment(acc1[i][jj], 0.f);
            }
#pragma unroll
            for (int ks = 0; ks < 2; ks++) {
                wmma::fragment<wmma::matrix_a, 16, 16, 16, __half, wmma::row_major> af[2];
                wmma::fragment<wmma::matrix_b, 16, 16, 16, __half, wmma::col_major> bf[2];
#pragma unroll
                for (int i = 0; i < 2; i++)
                    wmma::load_matrix_sync(af[i], x1 + (wm1 * 32 + i * 16) * A_LD + ph * 32 + ks * 16, A_LD);
#pragma unroll
                for (int jj = 0; jj < 2; jj++)
                    wmma::load_matrix_sync(bf[jj], Wb + (wn1 * 32 + jj * 16) * A_WLD + ks * 16, A_WLD);
#pragma unroll
                for (int i = 0; i < 2; i++)
#pragma unroll
                    for (int jj = 0; jj < 2; jj++)
                        wmma::mma_sync(acc1[i][jj], af[i], bf[jj], acc1[i][jj]);
            }
            if (ph == 3) {
#pragma unroll
                for (int i = 0; i < 2; i++)
#pragma unroll
                    for (int jj = 0; jj < 2; jj++)
                        wmma::store_matrix_sync(stg + (wm1 * 32 + i * 16) * 68 + wn1 * 32 + jj * 16,
                                                acc1[i][jj], 68, wmma::mem_row_major);
                __syncthreads();
                const float* bc = b1 + c * 64;
#pragma unroll
                for (int q = 0; q < 16; q++) {
                    int id = q * 256 + tid;
                    int row = id >> 5, col = (id & 31) * 2;
                    float v0 = fmaxf(stg[row * 68 + col]     + bc[col],     0.f);
                    float v1 = fmaxf(stg[row * 68 + col + 1] + bc[col + 1], 0.f);
                    *(__half2*)(hc + row * F_HLD + col) = __floats2half2_rn(v0, v1);
                }
            }
        } else {
            const int t2 = ph - 4;
#pragma unroll
            for (int ks = 0; ks < 2; ks++) {
                wmma::fragment<wmma::matrix_a, 16, 16, 16, __half, wmma::row_major> af[4];
                wmma::fragment<wmma::matrix_b, 16, 16, 16, __half, wmma::col_major> bf[2];
#pragma unroll
                for (int i = 0; i < 4; i++)
                    wmma::load_matrix_sync(af[i], hc + (wm2 * 64 + i * 16) * F_HLD + t2 * 32 + ks * 16, F_HLD);
#pragma unroll
                for (int jj = 0; jj < 2; jj++)
                    wmma::load_matrix_sync(bf[jj], Wb + (wn2 * 32 + jj * 16) * A_WLD + ks * 16, A_WLD);
#pragma unroll
                for (int i = 0; i < 4; i++)
#pragma unroll
                    for (int jj = 0; jj < 2; jj++)
                        wmma::mma_sync(acc[i][jj], af[i], bf[jj], acc[i][jj]);
            }
        }
        __syncthreads();
    }

    // ---- LN2 epilogue: residual from x1 (smem), write Xh (+X on last) ----
    float4 gv = *(const float4*)(g2  + lane * 4);
    float4 bv = *(const float4*)(be2 + lane * 4);
    float4 bz = *(const float4*)(b2  + lane * 4);
#pragma unroll
    for (int pass = 0; pass < 2; pass++) {
        if (wm2 == pass) {
#pragma unroll
            for (int i = 0; i < 4; i++)
#pragma unroll
                for (int jj = 0; jj < 2; jj++)
                    wmma::store_matrix_sync(stg + (i * 16) * 132 + wn2 * 32 + jj * 16,
                                            acc[i][jj], 132, wmma::mem_row_major);
        }
        __syncthreads();
#pragma unroll
        for (int rr = 0; rr < 8; rr++) {
            const int r64 = wid * 8 + rr;
            const int rloc = pass * 64 + r64;
            float4 v = *(float4*)(stg + r64 * 132 + lane * 4);
            const size_t off = (bm + rloc) * DD + lane * 4;
            uint2 ru = *(const uint2*)(x1 + rloc * A_LD + lane * 4);
            float2 x0 = __half22float2(*(const __half2*)&ru.x);
            float2 xx1 = __half22float2(*(const __half2*)&ru.y);
            float4 tv;
            tv.x = v.x + bz.x + x0.x; tv.y = v.y + bz.y + x0.y;
            tv.z = v.z + bz.z + xx1.x; tv.w = v.w + bz.w + xx1.y;
            float s  = tv.x + tv.y + tv.z + tv.w;
            float s2 = tv.x*tv.x + tv.y*tv.y + tv.z*tv.z + tv.w*tv.w;
#pragma unroll
            for (int o = 16; o > 0; o >>= 1) {
                s  += __shfl_xor_sync(0xffffffffu, s,  o);
                s2 += __shfl_xor_sync(0xffffffffu, s2, o);
            }
            float mean = s * (1.f / DD);
            float var  = s2 * (1.f / DD) - mean * mean;
            float rstd = rsqrtf(var + 1e-5f);
            float4 y;
            y.x = (tv.x - mean) * rstd * gv.x + bv.x;
            y.y = (tv.y - mean) * rstd * gv.y + bv.y;
            y.z = (tv.z - mean) * rstd * gv.z + bv.z;
            y.w = (tv.w - mean) * rstd * gv.w + bv.w;
            if (wx) *(float4*)(X + off) = y;
            __half2 h0 = __floats2half2_rn(y.x, y.y);
            __half2 h1 = __floats2half2_rn(y.z, y.w);
            uint2 u;
            u.x = *reinterpret_cast<uint32_t*>(&h0);
            u.y = *reinterpret_cast<uint32_t*>(&h1);
            *(uint2*)(Xh + off) = u;
        }
        __syncthreads();
    }
}

// ---------------------------------------------------------------------------
extern "C" void kernel_launch(void* const* d_in, const int* in_sizes, int n_in,
                              void* d_out, int out_size)
{
    const float* x_in      = (const float*)d_in[0];
    const float* mask      = (const float*)d_in[1];
    const float* in_proj_w = (const float*)d_in[2];
    const float* in_proj_b = (const float*)d_in[3];
    const float* out_w     = (const float*)d_in[4];
    const float* out_b     = (const float*)d_in[5];
    const float* ln1_g     = (const float*)d_in[6];
    const float* ln1_b     = (const float*)d_in[7];
    const float* ff1_w     = (const float*)d_in[8];
    const float* ff1_b     = (const float*)d_in[9];
    const float* ff2_w     = (const float*)d_in[10];
    const float* ff2_b     = (const float*)d_in[11];
    const float* ln2_g     = (const float*)d_in[12];
    const float* ln2_b     = (const float*)d_in[13];
    float* x = (float*)d_out;

    __half *wqkv, *wout, *wff1, *wff2, *xh, *qkvh, *attnh;
    cudaGetSymbolAddress((void**)&wqkv, g_wqkv);
    cudaGetSymbolAddress((void**)&wout, g_wout);
    cudaGetSymbolAddress((void**)&wff1, g_wff1);
    cudaGetSymbolAddress((void**)&wff2, g_wff2);
    cudaGetSymbolAddress((void**)&xh,   g_xh);
    cudaGetSymbolAddress((void**)&qkvh, g_qkvh);
    cudaGetSymbolAddress((void**)&attnh,g_attnh);

    cudaFuncSetAttribute(gemm_h,   cudaFuncAttributeMaxDynamicSharedMemorySize, SMEM_DYN);
    cudaFuncSetAttribute(attn_tc,  cudaFuncAttributeMaxDynamicSharedMemorySize, ATT_SMEM);
    cudaFuncSetAttribute(of_fused, cudaFuncAttributeMaxDynamicSharedMemorySize, F_SMEM);

    cvt_all<<<(N_CVT + 255) / 256, 256>>>(x_in, in_proj_w, out_w, ff1_w, ff2_w);

    for (int l = 0; l < NL; l++) {
        gemm_h<<<dim3(3, MM / 128), 256, SMEM_DYN>>>(
            xh, wqkv + (size_t)l * 3 * DD * DD, in_proj_b + (size_t)l * 3 * DD,
            qkvh, 3 * DD, DD);
        attn_tc<<<BB * HH, 256, ATT_SMEM>>>(qkvh, mask, attnh);
        of_fused<<<MM / 128, 256, F_SMEM>>>(
            attnh, wout + (size_t)l * DD * DD, out_b + (size_t)l * DD,
            ln1_g + (size_t)l * DD, ln1_b + (size_t)l * DD,
            wff1 + (size_t)l * FFD * DD, ff1_b + (size_t)l * FFD,
            wff2 + (size_t)l * DD * FFD, ff2_b + (size_t)l * DD,
            ln2_g + (size_t)l * DD, ln2_b + (size_t)l * DD,
            xh, x, (l == NL - 1) ? 1 : 0);
    }
}

// round 16
// speedup vs baseline: 1.6872x; 1.0086x over previous
#include <cuda_runtime.h>
#include <cuda_fp16.h>
#include <mma.h>
#include <cstdint>
using namespace nvcuda;

// Problem dims (fixed)
#define BB   1024
#define TT   128
#define DD   128
#define HH   8
#define HDIM 16
#define FFD  512
#define NL   2
#define MM   (BB*TT)          // 131072 tokens

// fp16 scratch
__device__ __half g_wqkv[(size_t)NL * 3 * DD * DD];
__device__ __half g_wout[(size_t)NL * DD * DD];
__device__ __half g_wff1[(size_t)NL * FFD * DD];
__device__ __half g_wff2[(size_t)NL * DD * FFD];
__device__ __half g_xh  [(size_t)MM * DD];
__device__ __half g_qkvh[(size_t)MM * 3 * DD];
__device__ __half g_attnh[(size_t)MM * DD];

// ---------------------------------------------------------------------------
#define N_XH4 (MM * DD / 4)
#define N_WQ4 (NL * 3 * DD * DD / 4)
#define N_WO4 (NL * DD * DD / 4)
#define N_W14 (NL * FFD * DD / 4)
#define N_W24 (NL * DD * FFD / 4)
#define N_CVT (N_XH4 + N_WQ4 + N_WO4 + N_W14 + N_W24)

__global__ void cvt_all(const float* __restrict__ x,
                        const float* __restrict__ wq,
                        const float* __restrict__ wo,
                        const float* __restrict__ w1,
                        const float* __restrict__ w2)
{
    long i = (long)blockIdx.x * blockDim.x + threadIdx.x;
    if (i >= N_CVT) return;
    const float* src;
    __half* dst;
    long off = i;
    if (off < N_XH4)                      { src = x;  dst = g_xh;   }
    else if ((off -= N_XH4) < N_WQ4)      { src = wq; dst = g_wqkv; }
    else if ((off -= N_WQ4) < N_WO4)      { src = wo; dst = g_wout; }
    else if ((off -= N_WO4) < N_W14)      { src = w1; dst = g_wff1; }
    else  { off -= N_W14;                   src = w2; dst = g_wff2; }
    float4 v = ((const float4*)src)[off];
    __half2 h0 = __floats2half2_rn(v.x, v.y);
    __half2 h1 = __floats2half2_rn(v.z, v.w);
    uint2 u;
    u.x = *reinterpret_cast<uint32_t*>(&h0);
    u.y = *reinterpret_cast<uint32_t*>(&h1);
    ((uint2*)dst)[off] = u;
}

__device__ __forceinline__ uint32_t smem_u32(const void* p) {
    uint32_t a;
    asm("{ .reg .u64 t; cvta.to.shared.u64 t, %1; cvt.u32.u64 %0, t; }"
        : "=r"(a) : "l"(p));
    return a;
}
__device__ __forceinline__ void cp16(uint32_t dst, const void* src) {
    asm volatile("cp.async.ca.shared.global [%0], [%1], 16;" :: "r"(dst), "l"(src));
}
__device__ __forceinline__ float fast_exp_s6(float x) {
    x = fmaxf(x, -80.f);
    float t  = x * 1.4426950408889634f;
    float fn = t + 12582912.f;
    int   ni = __float_as_int(fn) - 0x4B400000;
    float r  = t - (fn - 12582912.f);
    float p  = 0.00133336f;
    p = fmaf(p, r, 0.00961813f);
    p = fmaf(p, r, 0.05550411f);
    p = fmaf(p, r, 0.24022651f);
    p = fmaf(p, r, 0.69314718f);
    p = fmaf(p, r, 1.0f);
    return p * __int_as_float((ni + 121) << 23);   // * 2^(n-6)
}

// ---------------------------------------------------------------------------
// gemm_h: qkv projection, fp16 out. Single sync per K-iter (issue-after-sync).
// ---------------------------------------------------------------------------
#define BK   32
#define ALD  40
#define STG_B 20480
#define NS   4
#define CLD  132
#define SMEM_DYN (NS*STG_B)

__global__ __launch_bounds__(256, 2) void gemm_h(
    const __half* __restrict__ A, const __half* __restrict__ W,
    const float* __restrict__ bias, __half* __restrict__ Ch,
    int N, int K)
{
    extern __shared__ __align__(16) char smem[];
    const uint32_t sbase = smem_u32(smem);
    const int tid  = threadIdx.x;
    const int wid  = tid >> 5;
    const int wm   = wid & 1;
    const int wn   = wid >> 1;
    const size_t bm = (size_t)blockIdx.y * 128;
    const size_t bn = (size_t)blockIdx.x * 128;
    const int NT = K / BK;

    const int rA0 = tid >> 2, cA0 = tid & 3;
    const int rA1 = (tid + 256) >> 2, cA1 = (tid + 256) & 3;

    wmma::fragment<wmma::accumulator, 16, 16, 16, float> acc[4][2];
#pragma unroll
    for (int i = 0; i < 4; i++)
#pragma unroll
        for (int j = 0; j < 2; j++) wmma::fill_fragment(acc[i][j], 0.f);

#pragma unroll
    for (int t = 0; t < NS - 1; t++) {
        if (t < NT) {
            const int kk = t * BK;
            const uint32_t sb = sbase + (t % NS) * STG_B;
            cp16(sb + (rA0 * ALD + cA0 * 8) * 2, A + (bm + rA0) * K + kk + cA0 * 8);
            cp16(sb + (rA1 * ALD + cA1 * 8) * 2, A + (bm + rA1) * K + kk + cA1 * 8);
            cp16(sb + 10240 + (rA0 * ALD + cA0 * 8) * 2, W + (bn + rA0) * K + kk + cA0 * 8);
            cp16(sb + 10240 + (rA1 * ALD + cA1 * 8) * 2, W + (bn + rA1) * K + kk + cA1 * 8);
        }
        asm volatile("cp.async.commit_group;");
    }

    for (int t = 0; t < NT; t++) {
        asm volatile("cp.async.wait_group %0;" :: "n"(NS - 2));
        __syncthreads();
        // issue t+NS-1 after the sync (buffer last read at t-1, now safe)
        {
            const int tn = t + NS - 1;
            if (tn < NT) {
                const int kk = tn * BK;
                const uint32_t sb = sbase + (tn % NS) * STG_B;
                cp16(sb + (rA0 * ALD + cA0 * 8) * 2, A + (bm + rA0) * K + kk + cA0 * 8);
                cp16(sb + (rA1 * ALD + cA1 * 8) * 2, A + (bm + rA1) * K + kk + cA1 * 8);
                cp16(sb + 10240 + (rA0 * ALD + cA0 * 8) * 2, W + (bn + rA0) * K + kk + cA0 * 8);
                cp16(sb + 10240 + (rA1 * ALD + cA1 * 8) * 2, W + (bn + rA1) * K + kk + cA1 * 8);
            }
            asm volatile("cp.async.commit_group;");
        }
        {
            const __half* As = (const __half*)(smem + (t % NS) * STG_B);
            const __half* Ws = As + 5120;
#pragma unroll
            for (int ks = 0; ks < 2; ks++) {
                wmma::fragment<wmma::matrix_a, 16, 16, 16, __half, wmma::row_major> af[4];
                wmma::fragment<wmma::matrix_b, 16, 16, 16, __half, wmma::col_major> bf[2];
#pragma unroll
                for (int i = 0; i < 4; i++)
                    wmma::load_matrix_sync(af[i], As + (wm * 64 + i * 16) * ALD + ks * 16, ALD);
#pragma unroll
                for (int j = 0; j < 2; j++)
                    wmma::load_matrix_sync(bf[j], Ws + (wn * 32 + j * 16) * ALD + ks * 16, ALD);
#pragma unroll
                for (int i = 0; i < 4; i++)
#pragma unroll
                    for (int j = 0; j < 2; j++)
                        wmma::mma_sync(acc[i][j], af[i], bf[j], acc[i][j]);
            }
        }
    }
    __syncthreads();

    float* smf = (float*)smem;
#pragma unroll
    for (int i = 0; i < 4; i++)
#pragma unroll
        for (int j = 0; j < 2; j++)
            wmma::store_matrix_sync(smf + (wm * 64 + i * 16) * CLD + wn * 32 + j * 16,
                                    acc[i][j], CLD, wmma::mem_row_major);
    __syncthreads();

#pragma unroll
    for (int i = 0; i < 16; i++) {
        int idx = i * 256 + tid;
        int row = idx >> 5;
        int cc  = (idx & 31) * 4;
        float4 v  = *(float4*)(smf + row * CLD + cc);
        float4 bz = *(const float4*)(bias + bn + cc);
        v.x += bz.x; v.y += bz.y; v.z += bz.z; v.w += bz.w;
        __half2 h0 = __floats2half2_rn(v.x, v.y);
        __half2 h1 = __floats2half2_rn(v.z, v.w);
        uint2 u;
        u.x = *reinterpret_cast<uint32_t*>(&h0);
        u.y = *reinterpret_cast<uint32_t*>(&h1);
        *(uint2*)(Ch + (bm + row) * N + bn + cc) = u;
    }
}

// ---------------------------------------------------------------------------
// attn_tc: one block per (b,h), 256 threads / 8 warps, 2 CTA/SM.
// ---------------------------------------------------------------------------
#define QLD 24
#define SLD 68
#define PLD 136
#define OLD 20
#define ATT_SMEM 89088

__global__ __launch_bounds__(256, 2) void attn_tc(
    const __half* __restrict__ qkv, const float* __restrict__ mask,
    __half* __restrict__ out)
{
    extern __shared__ __align__(16) char asmem[];
    __half* Qs = (__half*)(asmem);
    __half* Ks = (__half*)(asmem + 6144);
    __half* Vs = (__half*)(asmem + 12288);
    float*  ms = (float*) (asmem + 18432);
    float*  rs = (float*) (asmem + 18944);
    float*  Ss = (float*) (asmem + 19456);
    __half* Ps = (__half*)(asmem + 54272);
    float*  Os = (float*) (asmem);

    const int h = blockIdx.x & 7;
    const int b = blockIdx.x >> 3;
    const int tid = threadIdx.x, wid = tid >> 5;

    {
        const int row = tid >> 1, ch = tid & 1;
        const __half* base = qkv + ((size_t)b * TT + row) * (3 * DD) + h * HDIM + ch * 8;
        *(uint4*)(Qs + row * QLD + ch * 8) = *(const uint4*)(base);
        *(uint4*)(Ks + row * QLD + ch * 8) = *(const uint4*)(base + DD);
        *(uint4*)(Vs + row * QLD + ch * 8) = *(const uint4*)(base + 2 * DD);
        if (tid < TT) ms[tid] = mask[b * TT + tid];
    }
    __syncthreads();

    wmma::fragment<wmma::matrix_a, 16, 16, 16, __half, wmma::row_major> qf;
    wmma::load_matrix_sync(qf, Qs + wid * 16 * QLD, QLD);

    float sum = 0.f;
    const int er = tid >> 1;
    const int eh = tid & 1;

    for (int chunk = 0; chunk < 2; chunk++) {
#pragma unroll
        for (int j = 0; j < 4; j++) {
            wmma::fragment<wmma::matrix_b, 16, 16, 16, __half, wmma::col_major> kf;
            wmma::fragment<wmma::accumulator, 16, 16, 16, float> sf;
            wmma::load_matrix_sync(kf, Ks + (chunk * 64 + j * 16) * QLD, QLD);
            wmma::fill_fragment(sf, 0.f);
            wmma::mma_sync(sf, qf, kf, sf);
            wmma::store_matrix_sync(Ss + (wid * 16) * SLD + j * 16, sf, SLD, wmma::mem_row_major);
        }
        __syncthreads();
        {
            const float* srow = Ss + er * SLD + eh * 32;
            __half* prow = Ps + er * PLD + chunk * 64 + eh * 32;
            const float* mrow = ms + chunk * 64 + eh * 32;
#pragma unroll
            for (int c = 0; c < 32; c++) {
                float p = fast_exp_s6(fmaf(srow[c], 0.25f, mrow[c]));
                __half ph = __float2half_rn(p);
                prow[c] = ph;
                sum += __half2float(ph);
            }
        }
        __syncthreads();
    }
    sum += __shfl_xor_sync(0xffffffffu, sum, 1);
    if (!eh) rs[er] = sum;
    __syncthreads();

    {
        wmma::fragment<wmma::accumulator, 16, 16, 16, float> of;
        wmma::fill_fragment(of, 0.f);
#pragma unroll
        for (int j = 0; j < 8; j++) {
            wmma::fragment<wmma::matrix_a, 16, 16, 16, __half, wmma::row_major> pf;
            wmma::fragment<wmma::matrix_b, 16, 16, 16, __half, wmma::row_major> vf;
            wmma::load_matrix_sync(pf, Ps + (wid * 16) * PLD + j * 16, PLD);
            wmma::load_matrix_sync(vf, Vs + (j * 16) * QLD, QLD);
            wmma::mma_sync(of, pf, vf, of);
        }
        wmma::store_matrix_sync(Os + (wid * 16) * OLD, of, OLD, wmma::mem_row_major);
    }
    __syncthreads();

    {
        const int r = tid >> 1, c0 = (tid & 1) * 8;
        const float inv = 1.f / rs[r];
        const float* orow = Os + r * OLD + c0;
        uint4 u;
        uint32_t* pu = &u.x;
#pragma unroll
        for (int j = 0; j < 4; j++) {
            __half2 hv = __floats2half2_rn(orow[j * 2] * inv, orow[j * 2 + 1] * inv);
            pu[j] = *reinterpret_cast<uint32_t*>(&hv);
        }
        *(uint4*)(out + ((size_t)b * TT + r) * DD + h * HDIM + c0) = u;
    }
}

// ===========================================================================
// of_fused: per 128-token tile:
//   x1 = LN1(xh + attnh @ Wo^T + bo)                 (stays in smem)
//   Xh = LN2(x1 + relu(x1@W1^T+b1) @ W2^T + b2)      (+ X fp32 on last layer)
// Single __syncthreads per phase (issue-after-sync, 2-deep ring).
// ===========================================================================
#define A_LD    136
#define A_WLD   40
#define R1_OFF  34816
#define HC_OFF  69632
#define WB_OFF  88064
#define F_SMEM  108544
#define F_HLD   72

__global__ __launch_bounds__(256, 2) void of_fused(
    const __half* __restrict__ attnh, const __half* __restrict__ wo,
    const float* __restrict__ bo,
    const float* __restrict__ g1, const float* __restrict__ be1,
    const __half* __restrict__ w1, const float* __restrict__ b1,
    const __half* __restrict__ w2, const float* __restrict__ b2,
    const float* __restrict__ g2, const float* __restrict__ be2,
    __half* __restrict__ Xh, float* __restrict__ X, int wx)
{
    extern __shared__ __align__(16) char sm[];
    const uint32_t sb = smem_u32(sm);
    const int tid  = threadIdx.x;
    const int wid  = tid >> 5;
    const int lane = tid & 31;
    const size_t bm = (size_t)blockIdx.x * 128;

    const int wm1 = wid & 3, wn1 = wid >> 2;   // FF1: 4x2 warps, 32x32
    const int wm2 = wid & 1, wn2 = wid >> 1;   // outproj/FF2: 2x4 warps, 64x32

    const int r1 = tid >> 2, c4 = tid & 3;
    const uint32_t wdst0 = (r1 * A_WLD + c4 * 8) * 2;
    const uint32_t wdst1 = ((r1 + 64) * A_WLD + c4 * 8) * 2;
    const __half* wop0 = wo + (size_t)r1 * DD + c4 * 8;
    const __half* wop1 = wo + (size_t)(r1 + 64) * DD + c4 * 8;
    const __half* w1p  = w1 + (size_t)r1 * DD + c4 * 8;
    const __half* w2p0 = w2 + (size_t)r1 * FFD + c4 * 8;
    const __half* w2p1 = w2 + (size_t)(r1 + 64) * FFD + c4 * 8;

    // prologue: attnh tile (R0) + residual xh tile (R1), then Wo tile 0
    {
#pragma unroll
        for (int p = 0; p < 8; p++) {
            int id = p * 256 + tid;
            int row = id >> 4, c = id & 15;
            cp16(sb + row * (A_LD * 2) + c * 16, attnh + (bm + row) * DD + c * 8);
            cp16(sb + R1_OFF + row * (A_LD * 2) + c * 16, Xh + (bm + row) * DD + c * 8);
        }
        asm volatile("cp.async.commit_group;");
    }
    cp16(sb + WB_OFF + wdst0, wop0);
    cp16(sb + WB_OFF + wdst1, wop1);
    asm volatile("cp.async.commit_group;");

    const __half* As  = (const __half*)sm;            // attnh tile
    __half* x1 = (__half*)(sm + R1_OFF);              // residual -> LN1 out
    float* stg = (float*)sm;                          // staging (aliases As)
    __half* hc = (__half*)(sm + HC_OFF);

    // ---- loop A: out-proj (4 phases, one sync each) ----
    {
        wmma::fragment<wmma::accumulator, 16, 16, 16, float> aop[4][2];
#pragma unroll
        for (int i = 0; i < 4; i++)
#pragma unroll
            for (int jj = 0; jj < 2; jj++) wmma::fill_fragment(aop[i][jj], 0.f);

#pragma unroll
        for (int j = 0; j < 4; j++) {
            asm volatile("cp.async.wait_group 0;");
            __syncthreads();
            // issue next after sync (buffer last read at j-1)
            {
                const uint32_t wb = sb + WB_OFF + ((j + 1) & 1) * 10240;
                if (j < 3) {
                    cp16(wb + wdst0, wop0 + (j + 1) * 32);
                    cp16(wb + wdst1, wop1 + (j + 1) * 32);
                } else {
                    cp16(wb + wdst0, w1p);       // FF tile 0 (W1 c=0 ph=0)
                }
                asm volatile("cp.async.commit_group;");
            }
            const __half* Wb = (const __half*)(sm + WB_OFF + (j & 1) * 10240);
#pragma unroll
            for (int ks = 0; ks < 2; ks++) {
                wmma::fragment<wmma::matrix_a, 16, 16, 16, __half, wmma::row_major> af[4];
                wmma::fragment<wmma::matrix_b, 16, 16, 16, __half, wmma::col_major> bf[2];
#pragma unroll
                for (int i = 0; i < 4; i++)
                    wmma::load_matrix_sync(af[i], As + (wm2 * 64 + i * 16) * A_LD + j * 32 + ks * 16, A_LD);
#pragma unroll
                for (int jj = 0; jj < 2; jj++)
                    wmma::load_matrix_sync(bf[jj], Wb + (wn2 * 32 + jj * 16) * A_WLD + ks * 16, A_WLD);
#pragma unroll
                for (int i = 0; i < 4; i++)
#pragma unroll
                    for (int jj = 0; jj < 2; jj++)
                        wmma::mma_sync(aop[i][jj], af[i], bf[jj], aop[i][jj]);
            }
        }
        __syncthreads();   // all reads of As done before LN1 staging reuses it

        // ---- LN1 epilogue: stage 64 rows at a time into R0, fold residual ----
        float4 gv = *(const float4*)(g1  + lane * 4);
        float4 bv = *(const float4*)(be1 + lane * 4);
        float4 bz = *(const float4*)(bo  + lane * 4);
#pragma unroll
        for (int pass = 0; pass < 2; pass++) {
            if (wm2 == pass) {
#pragma unroll
                for (int i = 0; i < 4; i++)
#pragma unroll
                    for (int jj = 0; jj < 2; jj++)
                        wmma::store_matrix_sync(stg + (i * 16) * 132 + wn2 * 32 + jj * 16,
                                                aop[i][jj], 132, wmma::mem_row_major);
            }
            __syncthreads();
#pragma unroll
            for (int rr = 0; rr < 8; rr++) {
                const int r64 = wid * 8 + rr;
                const int rloc = pass * 64 + r64;
                float4 v = *(float4*)(stg + r64 * 132 + lane * 4);
                uint2 ru = *(const uint2*)(x1 + rloc * A_LD + lane * 4);
                float2 x0 = __half22float2(*(const __half2*)&ru.x);
                float2 xx1 = __half22float2(*(const __half2*)&ru.y);
                float4 tv;
                tv.x = v.x + bz.x + x0.x; tv.y = v.y + bz.y + x0.y;
                tv.z = v.z + bz.z + xx1.x; tv.w = v.w + bz.w + xx1.y;
                float s  = tv.x + tv.y + tv.z + tv.w;
                float s2 = tv.x*tv.x + tv.y*tv.y + tv.z*tv.z + tv.w*tv.w;
#pragma unroll
                for (int o = 16; o > 0; o >>= 1) {
                    s  += __shfl_xor_sync(0xffffffffu, s,  o);
                    s2 += __shfl_xor_sync(0xffffffffu, s2, o);
                }
                float mean = s * (1.f / DD);
                float var  = s2 * (1.f / DD) - mean * mean;
                float rstd = rsqrtf(var + 1e-5f);
                float4 y;
                y.x = (tv.x - mean) * rstd * gv.x + bv.x;
                y.y = (tv.y - mean) * rstd * gv.y + bv.y;
                y.z = (tv.z - mean) * rstd * gv.z + bv.z;
                y.w = (tv.w - mean) * rstd * gv.w + bv.w;
                __half2 h0 = __floats2half2_rn(y.x, y.y);
                __half2 h1 = __floats2half2_rn(y.z, y.w);
                uint2 u;
                u.x = *reinterpret_cast<uint32_t*>(&h0);
                u.y = *reinterpret_cast<uint32_t*>(&h1);
                *(uint2*)(x1 + rloc * A_LD + lane * 4) = u;   // in-place
            }
            __syncthreads();
        }
    }

    // ---- loop B: FF (48 phases, one sync each), A operand = x1 (smem) ----
    wmma::fragment<wmma::accumulator, 16, 16, 16, float> acc[4][2];
#pragma unroll
    for (int i = 0; i < 4; i++)
#pragma unroll
        for (int jj = 0; jj < 2; jj++) wmma::fill_fragment(acc[i][jj], 0.f);
    wmma::fragment<wmma::accumulator, 16, 16, 16, float> acc1[2][2];

    int cn = 0, phn = 0;   // next-issue counters (track jb+1)
    for (int jb = 0; jb < 48; jb++) {
        const int c = cn, ph = phn;
        asm volatile("cp.async.wait_group 0;");
        __syncthreads();
        if (jb < 47) {
            if (++phn == 6) { phn = 0; cn++; }
            const uint32_t wb = sb + WB_OFF + ((jb + 1) & 1) * 10240;
            if (phn < 4) {
                cp16(wb + wdst0, w1p + (size_t)cn * 64 * DD + phn * 32);
            } else {
                const int t2 = phn - 4;
                cp16(wb + wdst0, w2p0 + cn * 64 + t2 * 32);
                cp16(wb + wdst1, w2p1 + cn * 64 + t2 * 32);
            }
            asm volatile("cp.async.commit_group;");
        }

        const __half* Wb = (const __half*)(sm + WB_OFF + (jb & 1) * 10240);
        if (ph < 4) {
            if (ph == 0) {
#pragma unroll
                for (int i = 0; i < 2; i++)
#pragma unroll
                    for (int jj = 0; jj < 2; jj++) wmma::fill_fragment(acc1[i][jj], 0.f);
            }
#pragma unroll
            for (int ks = 0; ks < 2; ks++) {
                wmma::fragment<wmma::matrix_a, 16, 16, 16, __half, wmma::row_major> af[2];
                wmma::fragment<wmma::matrix_b, 16, 16, 16, __half, wmma::col_major> bf[2];
#pragma unroll
                for (int i = 0; i < 2; i++)
                    wmma::load_matrix_sync(af[i], x1 + (wm1 * 32 + i * 16) * A_LD + ph * 32 + ks * 16, A_LD);
#pragma unroll
                for (int jj = 0; jj < 2; jj++)
                    wmma::load_matrix_sync(bf[jj], Wb + (wn1 * 32 + jj * 16) * A_WLD + ks * 16, A_WLD);
#pragma unroll
                for (int i = 0; i < 2; i++)
#pragma unroll
                    for (int jj = 0; jj < 2; jj++)
                        wmma::mma_sync(acc1[i][jj], af[i], bf[jj], acc1[i][jj]);
            }
            if (ph == 3) {
#pragma unroll
                for (int i = 0; i < 2; i++)
#pragma unroll
                    for (int jj = 0; jj < 2; jj++)
                        wmma::store_matrix_sync(stg + (wm1 * 32 + i * 16) * 68 + wn1 * 32 + jj * 16,
                                                acc1[i][jj], 68, wmma::mem_row_major);
                __syncthreads();
                const float* bc = b1 + c * 64;
#pragma unroll
                for (int q = 0; q < 16; q++) {
                    int id = q * 256 + tid;
                    int row = id >> 5, col = (id & 31) * 2;
                    float v0 = fmaxf(stg[row * 68 + col]     + bc[col],     0.f);
                    float v1 = fmaxf(stg[row * 68 + col + 1] + bc[col + 1], 0.f);
                    *(__half2*)(hc + row * F_HLD + col) = __floats2half2_rn(v0, v1);
                }
            }
        } else {
            const int t2 = ph - 4;
#pragma unroll
            for (int ks = 0; ks < 2; ks++) {
                wmma::fragment<wmma::matrix_a, 16, 16, 16, __half, wmma::row_major> af[4];
                wmma::fragment<wmma::matrix_b, 16, 16, 16, __half, wmma::col_major> bf[2];
#pragma unroll
                for (int i = 0; i < 4; i++)
                    wmma::load_matrix_sync(af[i], hc + (wm2 * 64 + i * 16) * F_HLD + t2 * 32 + ks * 16, F_HLD);
#pragma unroll
                for (int jj = 0; jj < 2; jj++)
                    wmma::load_matrix_sync(bf[jj], Wb + (wn2 * 32 + jj * 16) * A_WLD + ks * 16, A_WLD);
#pragma unroll
                for (int i = 0; i < 4; i++)
#pragma unroll
                    for (int jj = 0; jj < 2; jj++)
                        wmma::mma_sync(acc[i][jj], af[i], bf[jj], acc[i][jj]);
            }
        }
    }
    __syncthreads();

    // ---- LN2 epilogue: residual from x1 (smem), write Xh (+X on last) ----
    float4 gv = *(const float4*)(g2  + lane * 4);
    float4 bv = *(const float4*)(be2 + lane * 4);
    float4 bz = *(const float4*)(b2  + lane * 4);
#pragma unroll
    for (int pass = 0; pass < 2; pass++) {
        if (wm2 == pass) {
#pragma unroll
            for (int i = 0; i < 4; i++)
#pragma unroll
                for (int jj = 0; jj < 2; jj++)
                    wmma::store_matrix_sync(stg + (i * 16) * 132 + wn2 * 32 + jj * 16,
                                            acc[i][jj], 132, wmma::mem_row_major);
        }
        __syncthreads();
#pragma unroll
        for (int rr = 0; rr < 8; rr++) {
            const int r64 = wid * 8 + rr;
            const int rloc = pass * 64 + r64;
            float4 v = *(float4*)(stg + r64 * 132 + lane * 4);
            const size_t off = (bm + rloc) * DD + lane * 4;
            uint2 ru = *(const uint2*)(x1 + rloc * A_LD + lane * 4);
            float2 x0 = __half22float2(*(const __half2*)&ru.x);
            float2 xx1 = __half22float2(*(const __half2*)&ru.y);
            float4 tv;
            tv.x = v.x + bz.x + x0.x; tv.y = v.y + bz.y + x0.y;
            tv.z = v.z + bz.z + xx1.x; tv.w = v.w + bz.w + xx1.y;
            float s  = tv.x + tv.y + tv.z + tv.w;
            float s2 = tv.x*tv.x + tv.y*tv.y + tv.z*tv.z + tv.w*tv.w;
#pragma unroll
            for (int o = 16; o > 0; o >>= 1) {
                s  += __shfl_xor_sync(0xffffffffu, s,  o);
                s2 += __shfl_xor_sync(0xffffffffu, s2, o);
            }
            float mean = s * (1.f / DD);
            float var  = s2 * (1.f / DD) - mean * mean;
            float rstd = rsqrtf(var + 1e-5f);
            float4 y;
            y.x = (tv.x - mean) * rstd * gv.x + bv.x;
            y.y = (tv.y - mean) * rstd * gv.y + bv.y;
            y.z = (tv.z - mean) * rstd * gv.z + bv.z;
            y.w = (tv.w - mean) * rstd * gv.w + bv.w;
            if (wx) *(float4*)(X + off) = y;
            __half2 h0 = __floats2half2_rn(y.x, y.y);
            __half2 h1 = __floats2half2_rn(y.z, y.w);
            uint2 u;
            u.x = *reinterpret_cast<uint32_t*>(&h0);
            u.y = *reinterpret_cast<uint32_t*>(&h1);
            *(uint2*)(Xh + off) = u;
        }
        __syncthreads();
    }
}

// ---------------------------------------------------------------------------
extern "C" void kernel_launch(void* const* d_in, const int* in_sizes, int n_in,
                              void* d_out, int out_size)
{
    const float* x_in      = (const float*)d_in[0];
    const float* mask      = (const float*)d_in[1];
    const float* in_proj_w = (const float*)d_in[2];
    const float* in_proj_b = (const float*)d_in[3];
    const float* out_w     = (const float*)d_in[4];
    const float* out_b     = (const float*)d_in[5];
    const float* ln1_g     = (const float*)d_in[6];
    const float* ln1_b     = (const float*)d_in[7];
    const float* ff1_w     = (const float*)d_in[8];
    const float* ff1_b     = (const float*)d_in[9];
    const float* ff2_w     = (const float*)d_in[10];
    const float* ff2_b     = (const float*)d_in[11];
    const float* ln2_g     = (const float*)d_in[12];
    const float* ln2_b     = (const float*)d_in[13];
    float* x = (float*)d_out;

    __half *wqkv, *wout, *wff1, *wff2, *xh, *qkvh, *attnh;
    cudaGetSymbolAddress((void**)&wqkv, g_wqkv);
    cudaGetSymbolAddress((void**)&wout, g_wout);
    cudaGetSymbolAddress((void**)&wff1, g_wff1);
    cudaGetSymbolAddress((void**)&wff2, g_wff2);
    cudaGetSymbolAddress((void**)&xh,   g_xh);
    cudaGetSymbolAddress((void**)&qkvh, g_qkvh);
    cudaGetSymbolAddress((void**)&attnh,g_attnh);

    cudaFuncSetAttribute(gemm_h,   cudaFuncAttributeMaxDynamicSharedMemorySize, SMEM_DYN);
    cudaFuncSetAttribute(attn_tc,  cudaFuncAttributeMaxDynamicSharedMemorySize, ATT_SMEM);
    cudaFuncSetAttribute(of_fused, cudaFuncAttributeMaxDynamicSharedMemorySize, F_SMEM);

    cvt_all<<<(N_CVT + 255) / 256, 256>>>(x_in, in_proj_w, out_w, ff1_w, ff2_w);

    for (int l = 0; l < NL; l++) {
        gemm_h<<<dim3(3, MM / 128), 256, SMEM_DYN>>>(
            xh, wqkv + (size_t)l * 3 * DD * DD, in_proj_b + (size_t)l * 3 * DD,
            qkvh, 3 * DD, DD);
        attn_tc<<<BB * HH, 256, ATT_SMEM>>>(qkvh, mask, attnh);
        of_fused<<<MM / 128, 256, F_SMEM>>>(
            attnh, wout + (size_t)l * DD * DD, out_b + (size_t)l * DD,
            ln1_g + (size_t)l * DD, ln1_b + (size_t)l * DD,
            wff1 + (size_t)l * FFD * DD, ff1_b + (size_t)l * FFD,
            wff2 + (size_t)l * DD * FFD, ff2_b + (size_t)l * DD,
            ln2_g + (size_t)l * DD, ln2_b + (size_t)l * DD,
            xh, x, (l == NL - 1) ? 1 : 0);
    }
}

// round 17
// speedup vs baseline: 1.7039x; 1.0099x over previous
#include <cuda_runtime.h>
#include <cuda_fp16.h>
#include <mma.h>
#include <cstdint>
using namespace nvcuda;

// Problem dims (fixed)
#define BB   1024
#define TT   128
#define DD   128
#define HH   8
#define HDIM 16
#define FFD  512
#define NL   2
#define MM   (BB*TT)          // 131072 tokens

// fp16 scratch
__device__ __half g_wqkv[(size_t)NL * 3 * DD * DD];
__device__ __half g_wout[(size_t)NL * DD * DD];
__device__ __half g_wff1[(size_t)NL * FFD * DD];
__device__ __half g_wff2[(size_t)NL * DD * FFD];
__device__ __half g_xh  [(size_t)MM * DD];
__device__ __half g_qkvh[(size_t)MM * 3 * DD];
__device__ __half g_attnh[(size_t)MM * DD];

// ---------------------------------------------------------------------------
#define N_XH4 (MM * DD / 4)
#define N_WQ4 (NL * 3 * DD * DD / 4)
#define N_WO4 (NL * DD * DD / 4)
#define N_W14 (NL * FFD * DD / 4)
#define N_W24 (NL * DD * FFD / 4)
#define N_CVT (N_XH4 + N_WQ4 + N_WO4 + N_W14 + N_W24)

__global__ void cvt_all(const float* __restrict__ x,
                        const float* __restrict__ wq,
                        const float* __restrict__ wo,
                        const float* __restrict__ w1,
                        const float* __restrict__ w2)
{
    long i = (long)blockIdx.x * blockDim.x + threadIdx.x;
    if (i >= N_CVT) return;
    const float* src;
    __half* dst;
    long off = i;
    if (off < N_XH4)                      { src = x;  dst = g_xh;   }
    else if ((off -= N_XH4) < N_WQ4)      { src = wq; dst = g_wqkv; }
    else if ((off -= N_WQ4) < N_WO4)      { src = wo; dst = g_wout; }
    else if ((off -= N_WO4) < N_W14)      { src = w1; dst = g_wff1; }
    else  { off -= N_W14;                   src = w2; dst = g_wff2; }
    float4 v = ((const float4*)src)[off];
    __half2 h0 = __floats2half2_rn(v.x, v.y);
    __half2 h1 = __floats2half2_rn(v.z, v.w);
    uint2 u;
    u.x = *reinterpret_cast<uint32_t*>(&h0);
    u.y = *reinterpret_cast<uint32_t*>(&h1);
    ((uint2*)dst)[off] = u;
}

__device__ __forceinline__ uint32_t smem_u32(const void* p) {
    uint32_t a;
    asm("{ .reg .u64 t; cvta.to.shared.u64 t, %1; cvt.u32.u64 %0, t; }"
        : "=r"(a) : "l"(p));
    return a;
}
__device__ __forceinline__ void cp16(uint32_t dst, const void* src) {
    asm volatile("cp.async.ca.shared.global [%0], [%1], 16;" :: "r"(dst), "l"(src));
}
__device__ __forceinline__ float fast_exp_s6(float x) {
    x = fmaxf(x, -80.f);
    float t  = x * 1.4426950408889634f;
    float fn = t + 12582912.f;
    int   ni = __float_as_int(fn) - 0x4B400000;
    float r  = t - (fn - 12582912.f);
    float p  = 0.00133336f;
    p = fmaf(p, r, 0.00961813f);
    p = fmaf(p, r, 0.05550411f);
    p = fmaf(p, r, 0.24022651f);
    p = fmaf(p, r, 0.69314718f);
    p = fmaf(p, r, 1.0f);
    return p * __int_as_float((ni + 121) << 23);   // * 2^(n-6)
}

// ---------------------------------------------------------------------------
// gemm_h: qkv projection, fp16 out (R16 proven).
// ---------------------------------------------------------------------------
#define BK   32
#define ALD  40
#define STG_B 20480
#define NS   4
#define CLD  132
#define SMEM_DYN (NS*STG_B)

__global__ __launch_bounds__(256, 2) void gemm_h(
    const __half* __restrict__ A, const __half* __restrict__ W,
    const float* __restrict__ bias, __half* __restrict__ Ch,
    int N, int K)
{
    extern __shared__ __align__(16) char smem[];
    const uint32_t sbase = smem_u32(smem);
    const int tid  = threadIdx.x;
    const int wid  = tid >> 5;
    const int wm   = wid & 1;
    const int wn   = wid >> 1;
    const size_t bm = (size_t)blockIdx.y * 128;
    const size_t bn = (size_t)blockIdx.x * 128;
    const int NT = K / BK;

    const int rA0 = tid >> 2, cA0 = tid & 3;
    const int rA1 = (tid + 256) >> 2, cA1 = (tid + 256) & 3;

    wmma::fragment<wmma::accumulator, 16, 16, 16, float> acc[4][2];
#pragma unroll
    for (int i = 0; i < 4; i++)
#pragma unroll
        for (int j = 0; j < 2; j++) wmma::fill_fragment(acc[i][j], 0.f);

#pragma unroll
    for (int t = 0; t < NS - 1; t++) {
        if (t < NT) {
            const int kk = t * BK;
            const uint32_t sb = sbase + (t % NS) * STG_B;
            cp16(sb + (rA0 * ALD + cA0 * 8) * 2, A + (bm + rA0) * K + kk + cA0 * 8);
            cp16(sb + (rA1 * ALD + cA1 * 8) * 2, A + (bm + rA1) * K + kk + cA1 * 8);
            cp16(sb + 10240 + (rA0 * ALD + cA0 * 8) * 2, W + (bn + rA0) * K + kk + cA0 * 8);
            cp16(sb + 10240 + (rA1 * ALD + cA1 * 8) * 2, W + (bn + rA1) * K + kk + cA1 * 8);
        }
        asm volatile("cp.async.commit_group;");
    }

    for (int t = 0; t < NT; t++) {
        asm volatile("cp.async.wait_group %0;" :: "n"(NS - 2));
        __syncthreads();
        {
            const int tn = t + NS - 1;
            if (tn < NT) {
                const int kk = tn * BK;
                const uint32_t sb = sbase + (tn % NS) * STG_B;
                cp16(sb + (rA0 * ALD + cA0 * 8) * 2, A + (bm + rA0) * K + kk + cA0 * 8);
                cp16(sb + (rA1 * ALD + cA1 * 8) * 2, A + (bm + rA1) * K + kk + cA1 * 8);
                cp16(sb + 10240 + (rA0 * ALD + cA0 * 8) * 2, W + (bn + rA0) * K + kk + cA0 * 8);
                cp16(sb + 10240 + (rA1 * ALD + cA1 * 8) * 2, W + (bn + rA1) * K + kk + cA1 * 8);
            }
            asm volatile("cp.async.commit_group;");
        }
        {
            const __half* As = (const __half*)(smem + (t % NS) * STG_B);
            const __half* Ws = As + 5120;
#pragma unroll
            for (int ks = 0; ks < 2; ks++) {
                wmma::fragment<wmma::matrix_a, 16, 16, 16, __half, wmma::row_major> af[4];
                wmma::fragment<wmma::matrix_b, 16, 16, 16, __half, wmma::col_major> bf[2];
#pragma unroll
                for (int i = 0; i < 4; i++)
                    wmma::load_matrix_sync(af[i], As + (wm * 64 + i * 16) * ALD + ks * 16, ALD);
#pragma unroll
                for (int j = 0; j < 2; j++)
                    wmma::load_matrix_sync(bf[j], Ws + (wn * 32 + j * 16) * ALD + ks * 16, ALD);
#pragma unroll
                for (int i = 0; i < 4; i++)
#pragma unroll
                    for (int j = 0; j < 2; j++)
                        wmma::mma_sync(acc[i][j], af[i], bf[j], acc[i][j]);
            }
        }
    }
    __syncthreads();

    float* smf = (float*)smem;
#pragma unroll
    for (int i = 0; i < 4; i++)
#pragma unroll
        for (int j = 0; j < 2; j++)
            wmma::store_matrix_sync(smf + (wm * 64 + i * 16) * CLD + wn * 32 + j * 16,
                                    acc[i][j], CLD, wmma::mem_row_major);
    __syncthreads();

#pragma unroll
    for (int i = 0; i < 16; i++) {
        int idx = i * 256 + tid;
        int row = idx >> 5;
        int cc  = (idx & 31) * 4;
        float4 v  = *(float4*)(smf + row * CLD + cc);
        float4 bz = *(const float4*)(bias + bn + cc);
        v.x += bz.x; v.y += bz.y; v.z += bz.z; v.w += bz.w;
        __half2 h0 = __floats2half2_rn(v.x, v.y);
        __half2 h1 = __floats2half2_rn(v.z, v.w);
        uint2 u;
        u.x = *reinterpret_cast<uint32_t*>(&h0);
        u.y = *reinterpret_cast<uint32_t*>(&h1);
        *(uint2*)(Ch + (bm + row) * N + bn + cc) = u;
    }
}

// ---------------------------------------------------------------------------
// attn_tc (proven): one block per (b,h), 256 threads / 8 warps, 2 CTA/SM.
// ---------------------------------------------------------------------------
#define QLD 24
#define SLD 68
#define PLD 136
#define OLD 20
#define ATT_SMEM 89088

__global__ __launch_bounds__(256, 2) void attn_tc(
    const __half* __restrict__ qkv, const float* __restrict__ mask,
    __half* __restrict__ out)
{
    extern __shared__ __align__(16) char asmem[];
    __half* Qs = (__half*)(asmem);
    __half* Ks = (__half*)(asmem + 6144);
    __half* Vs = (__half*)(asmem + 12288);
    float*  ms = (float*) (asmem + 18432);
    float*  rs = (float*) (asmem + 18944);
    float*  Ss = (float*) (asmem + 19456);
    __half* Ps = (__half*)(asmem + 54272);
    float*  Os = (float*) (asmem);

    const int h = blockIdx.x & 7;
    const int b = blockIdx.x >> 3;
    const int tid = threadIdx.x, wid = tid >> 5;

    {
        const int row = tid >> 1, ch = tid & 1;
        const __half* base = qkv + ((size_t)b * TT + row) * (3 * DD) + h * HDIM + ch * 8;
        *(uint4*)(Qs + row * QLD + ch * 8) = *(const uint4*)(base);
        *(uint4*)(Ks + row * QLD + ch * 8) = *(const uint4*)(base + DD);
        *(uint4*)(Vs + row * QLD + ch * 8) = *(const uint4*)(base + 2 * DD);
        if (tid < TT) ms[tid] = mask[b * TT + tid];
    }
    __syncthreads();

    wmma::fragment<wmma::matrix_a, 16, 16, 16, __half, wmma::row_major> qf;
    wmma::load_matrix_sync(qf, Qs + wid * 16 * QLD, QLD);

    float sum = 0.f;
    const int er = tid >> 1;
    const int eh = tid & 1;

    for (int chunk = 0; chunk < 2; chunk++) {
#pragma unroll
        for (int j = 0; j < 4; j++) {
            wmma::fragment<wmma::matrix_b, 16, 16, 16, __half, wmma::col_major> kf;
            wmma::fragment<wmma::accumulator, 16, 16, 16, float> sf;
            wmma::load_matrix_sync(kf, Ks + (chunk * 64 + j * 16) * QLD, QLD);
            wmma::fill_fragment(sf, 0.f);
            wmma::mma_sync(sf, qf, kf, sf);
            wmma::store_matrix_sync(Ss + (wid * 16) * SLD + j * 16, sf, SLD, wmma::mem_row_major);
        }
        __syncthreads();
        {
            const float* srow = Ss + er * SLD + eh * 32;
            __half* prow = Ps + er * PLD + chunk * 64 + eh * 32;
            const float* mrow = ms + chunk * 64 + eh * 32;
#pragma unroll
            for (int c = 0; c < 32; c++) {
                float p = fast_exp_s6(fmaf(srow[c], 0.25f, mrow[c]));
                __half ph = __float2half_rn(p);
                prow[c] = ph;
                sum += __half2float(ph);
            }
        }
        __syncthreads();
    }
    sum += __shfl_xor_sync(0xffffffffu, sum, 1);
    if (!eh) rs[er] = sum;
    __syncthreads();

    {
        wmma::fragment<wmma::accumulator, 16, 16, 16, float> of;
        wmma::fill_fragment(of, 0.f);
#pragma unroll
        for (int j = 0; j < 8; j++) {
            wmma::fragment<wmma::matrix_a, 16, 16, 16, __half, wmma::row_major> pf;
            wmma::fragment<wmma::matrix_b, 16, 16, 16, __half, wmma::row_major> vf;
            wmma::load_matrix_sync(pf, Ps + (wid * 16) * PLD + j * 16, PLD);
            wmma::load_matrix_sync(vf, Vs + (j * 16) * QLD, QLD);
            wmma::mma_sync(of, pf, vf, of);
        }
        wmma::store_matrix_sync(Os + (wid * 16) * OLD, of, OLD, wmma::mem_row_major);
    }
    __syncthreads();

    {
        const int r = tid >> 1, c0 = (tid & 1) * 8;
        const float inv = 1.f / rs[r];
        const float* orow = Os + r * OLD + c0;
        uint4 u;
        uint32_t* pu = &u.x;
#pragma unroll
        for (int j = 0; j < 4; j++) {
            __half2 hv = __floats2half2_rn(orow[j * 2] * inv, orow[j * 2 + 1] * inv);
            pu[j] = *reinterpret_cast<uint32_t*>(&hv);
        }
        *(uint4*)(out + ((size_t)b * TT + r) * DD + h * HDIM + c0) = u;
    }
}

// ===========================================================================
// of_fused: x1 = LN1(xh + attnh@Wo^T+bo); Xh = LN2(x1 + relu(x1@W1^T+b1)@W2^T+b2)
// Loop B: outer c (8) x fully-unrolled inner ph (6) -> constant-folded
// addressing, ring parity = ph&1 (compile-time). sync -> issue -> wait 1.
// ===========================================================================
#define A_LD    136
#define A_WLD   40
#define R1_OFF  34816
#define HC_OFF  69632
#define WB_OFF  88064
#define F_SMEM  108544
#define F_HLD   72

__global__ __launch_bounds__(256, 2) void of_fused(
    const __half* __restrict__ attnh, const __half* __restrict__ wo,
    const float* __restrict__ bo,
    const float* __restrict__ g1, const float* __restrict__ be1,
    const __half* __restrict__ w1, const float* __restrict__ b1,
    const __half* __restrict__ w2, const float* __restrict__ b2,
    const float* __restrict__ g2, const float* __restrict__ be2,
    __half* __restrict__ Xh, float* __restrict__ X, int wx)
{
    extern __shared__ __align__(16) char sm[];
    const uint32_t sb = smem_u32(sm);
    const int tid  = threadIdx.x;
    const int wid  = tid >> 5;
    const int lane = tid & 31;
    const size_t bm = (size_t)blockIdx.x * 128;

    const int wm1 = wid & 3, wn1 = wid >> 2;   // FF1: 4x2 warps, 32x32
    const int wm2 = wid & 1, wn2 = wid >> 1;   // outproj/FF2: 2x4 warps, 64x32

    const int r1 = tid >> 2, c4 = tid & 3;
    const uint32_t wdst0 = (r1 * A_WLD + c4 * 8) * 2;
    const uint32_t wdst1 = ((r1 + 64) * A_WLD + c4 * 8) * 2;
    const __half* wop0 = wo + (size_t)r1 * DD + c4 * 8;
    const __half* wop1 = wo + (size_t)(r1 + 64) * DD + c4 * 8;
    const __half* w1p  = w1 + (size_t)r1 * DD + c4 * 8;
    const __half* w2p0 = w2 + (size_t)r1 * FFD + c4 * 8;
    const __half* w2p1 = w2 + (size_t)(r1 + 64) * FFD + c4 * 8;

    // prologue: attnh tile (R0) + residual xh tile (R1), then Wo tile 0
    {
#pragma unroll
        for (int p = 0; p < 8; p++) {
            int id = p * 256 + tid;
            int row = id >> 4, c = id & 15;
            cp16(sb + row * (A_LD * 2) + c * 16, attnh + (bm + row) * DD + c * 8);
            cp16(sb + R1_OFF + row * (A_LD * 2) + c * 16, Xh + (bm + row) * DD + c * 8);
        }
        asm volatile("cp.async.commit_group;");
    }
    cp16(sb + WB_OFF + wdst0, wop0);
    cp16(sb + WB_OFF + wdst1, wop1);
    asm volatile("cp.async.commit_group;");

    const __half* As  = (const __half*)sm;
    __half* x1 = (__half*)(sm + R1_OFF);
    float* stg = (float*)sm;
    __half* hc = (__half*)(sm + HC_OFF);

    // ---- loop A: out-proj (4 phases) ----
    {
        wmma::fragment<wmma::accumulator, 16, 16, 16, float> aop[4][2];
#pragma unroll
        for (int i = 0; i < 4; i++)
#pragma unroll
            for (int jj = 0; jj < 2; jj++) wmma::fill_fragment(aop[i][jj], 0.f);

#pragma unroll
        for (int j = 0; j < 4; j++) {
            __syncthreads();
            {
                const uint32_t wb = sb + WB_OFF + ((j + 1) & 1) * 10240;
                if (j < 3) {
                    cp16(wb + wdst0, wop0 + (j + 1) * 32);
                    cp16(wb + wdst1, wop1 + (j + 1) * 32);
                } else {
                    cp16(wb + wdst0, w1p);       // FF tile 0 (W1 c=0 ph=0) -> buf 0
                }
                asm volatile("cp.async.commit_group;");
            }
            asm volatile("cp.async.wait_group 1;");
            __syncthreads();
            const __half* Wb = (const __half*)(sm + WB_OFF + (j & 1) * 10240);
#pragma unroll
            for (int ks = 0; ks < 2; ks++) {
                wmma::fragment<wmma::matrix_a, 16, 16, 16, __half, wmma::row_major> af[4];
                wmma::fragment<wmma::matrix_b, 16, 16, 16, __half, wmma::col_major> bf[2];
#pragma unroll
                for (int i = 0; i < 4; i++)
                    wmma::load_matrix_sync(af[i], As + (wm2 * 64 + i * 16) * A_LD + j * 32 + ks * 16, A_LD);
#pragma unroll
                for (int jj = 0; jj < 2; jj++)
                    wmma::load_matrix_sync(bf[jj], Wb + (wn2 * 32 + jj * 16) * A_WLD + ks * 16, A_WLD);
#pragma unroll
                for (int i = 0; i < 4; i++)
#pragma unroll
                    for (int jj = 0; jj < 2; jj++)
                        wmma::mma_sync(aop[i][jj], af[i], bf[jj], aop[i][jj]);
            }
        }
        __syncthreads();

        // LN1 epilogue (2 passes of 64 rows; in-place into x1)
        float4 gv = *(const float4*)(g1  + lane * 4);
        float4 bv = *(const float4*)(be1 + lane * 4);
        float4 bz = *(const float4*)(bo  + lane * 4);
#pragma unroll
        for (int pass = 0; pass < 2; pass++) {
            if (wm2 == pass) {
#pragma unroll
                for (int i = 0; i < 4; i++)
#pragma unroll
                    for (int jj = 0; jj < 2; jj++)
                        wmma::store_matrix_sync(stg + (i * 16) * 132 + wn2 * 32 + jj * 16,
                                                aop[i][jj], 132, wmma::mem_row_major);
            }
            __syncthreads();
#pragma unroll
            for (int rr = 0; rr < 8; rr++) {
                const int r64 = wid * 8 + rr;
                const int rloc = pass * 64 + r64;
                float4 v = *(float4*)(stg + r64 * 132 + lane * 4);
                uint2 ru = *(const uint2*)(x1 + rloc * A_LD + lane * 4);
                float2 x0 = __half22float2(*(const __half2*)&ru.x);
                float2 xx1 = __half22float2(*(const __half2*)&ru.y);
                float4 tv;
                tv.x = v.x + bz.x + x0.x; tv.y = v.y + bz.y + x0.y;
                tv.z = v.z + bz.z + xx1.x; tv.w = v.w + bz.w + xx1.y;
                float s  = tv.x + tv.y + tv.z + tv.w;
                float s2 = tv.x*tv.x + tv.y*tv.y + tv.z*tv.z + tv.w*tv.w;
#pragma unroll
                for (int o = 16; o > 0; o >>= 1) {
                    s  += __shfl_xor_sync(0xffffffffu, s,  o);
                    s2 += __shfl_xor_sync(0xffffffffu, s2, o);
                }
                float mean = s * (1.f / DD);
                float var  = s2 * (1.f / DD) - mean * mean;
                float rstd = rsqrtf(var + 1e-5f);
                float4 y;
                y.x = (tv.x - mean) * rstd * gv.x + bv.x;
                y.y = (tv.y - mean) * rstd * gv.y + bv.y;
                y.z = (tv.z - mean) * rstd * gv.z + bv.z;
                y.w = (tv.w - mean) * rstd * gv.w + bv.w;
                __half2 h0 = __floats2half2_rn(y.x, y.y);
                __half2 h1 = __floats2half2_rn(y.z, y.w);
                uint2 u;
                u.x = *reinterpret_cast<uint32_t*>(&h0);
                u.y = *reinterpret_cast<uint32_t*>(&h1);
                *(uint2*)(x1 + rloc * A_LD + lane * 4) = u;
            }
            __syncthreads();
        }
    }

    // ---- loop B: FF, outer c x unrolled ph (parity = ph&1, constant) ----
    wmma::fragment<wmma::accumulator, 16, 16, 16, float> acc[4][2];
#pragma unroll
    for (int i = 0; i < 4; i++)
#pragma unroll
        for (int jj = 0; jj < 2; jj++) wmma::fill_fragment(acc[i][jj], 0.f);
    wmma::fragment<wmma::accumulator, 16, 16, 16, float> acc1[2][2];

    for (int c = 0; c < 8; c++) {
#pragma unroll
        for (int ph = 0; ph < 6; ph++) {
            __syncthreads();
            // issue next phase (constant ph+1 addressing)
            if (!(c == 7 && ph == 5)) {
                const uint32_t wb = sb + WB_OFF + ((ph + 1) & 1) * 10240;
                if (ph < 3) {                     // next = W1 phase ph+1, same c
                    cp16(wb + wdst0, w1p + (size_t)c * 64 * DD + (ph + 1) * 32);
                } else if (ph == 3) {             // next = W2 t2=0
                    cp16(wb + wdst0, w2p0 + c * 64);
                    cp16(wb + wdst1, w2p1 + c * 64);
                } else if (ph == 4) {             // next = W2 t2=1
                    cp16(wb + wdst0, w2p0 + c * 64 + 32);
                    cp16(wb + wdst1, w2p1 + c * 64 + 32);
                } else {                          // next = W1 c+1 ph0
                    cp16(wb + wdst0, w1p + (size_t)(c + 1) * 64 * DD);
                }
                asm volatile("cp.async.commit_group;");
                asm volatile("cp.async.wait_group 1;");
            } else {
                asm volatile("cp.async.wait_group 0;");
            }
            __syncthreads();

            const __half* Wb = (const __half*)(sm + WB_OFF + (ph & 1) * 10240);
            if (ph < 4) {
                if (ph == 0) {
#pragma unroll
                    for (int i = 0; i < 2; i++)
#pragma unroll
                        for (int jj = 0; jj < 2; jj++) wmma::fill_fragment(acc1[i][jj], 0.f);
                }
#pragma unroll
                for (int ks = 0; ks < 2; ks++) {
                    wmma::fragment<wmma::matrix_a, 16, 16, 16, __half, wmma::row_major> af[2];
                    wmma::fragment<wmma::matrix_b, 16, 16, 16, __half, wmma::col_major> bf[2];
#pragma unroll
                    for (int i = 0; i < 2; i++)
                        wmma::load_matrix_sync(af[i], x1 + (wm1 * 32 + i * 16) * A_LD + ph * 32 + ks * 16, A_LD);
#pragma unroll
                    for (int jj = 0; jj < 2; jj++)
                        wmma::load_matrix_sync(bf[jj], Wb + (wn1 * 32 + jj * 16) * A_WLD + ks * 16, A_WLD);
#pragma unroll
                    for (int i = 0; i < 2; i++)
#pragma unroll
                        for (int jj = 0; jj < 2; jj++)
                            wmma::mma_sync(acc1[i][jj], af[i], bf[jj], acc1[i][jj]);
                }
                if (ph == 3) {
#pragma unroll
                    for (int i = 0; i < 2; i++)
#pragma unroll
                        for (int jj = 0; jj < 2; jj++)
                            wmma::store_matrix_sync(stg + (wm1 * 32 + i * 16) * 68 + wn1 * 32 + jj * 16,
                                                    acc1[i][jj], 68, wmma::mem_row_major);
                    __syncthreads();
                    const float* bc = b1 + c * 64;
#pragma unroll
                    for (int q = 0; q < 16; q++) {
                        int id = q * 256 + tid;
                        int row = id >> 5, col = (id & 31) * 2;
                        float v0 = fmaxf(stg[row * 68 + col]     + bc[col],     0.f);
                        float v1 = fmaxf(stg[row * 68 + col + 1] + bc[col + 1], 0.f);
                        *(__half2*)(hc + row * F_HLD + col) = __floats2half2_rn(v0, v1);
                    }
                }
            } else {
                const int t2 = ph - 4;
#pragma unroll
                for (int ks = 0; ks < 2; ks++) {
                    wmma::fragment<wmma::matrix_a, 16, 16, 16, __half, wmma::row_major> af[4];
                    wmma::fragment<wmma::matrix_b, 16, 16, 16, __half, wmma::col_major> bf[2];
#pragma unroll
                    for (int i = 0; i < 4; i++)
                        wmma::load_matrix_sync(af[i], hc + (wm2 * 64 + i * 16) * F_HLD + t2 * 32 + ks * 16, F_HLD);
#pragma unroll
                    for (int jj = 0; jj < 2; jj++)
                        wmma::load_matrix_sync(bf[jj], Wb + (wn2 * 32 + jj * 16) * A_WLD + ks * 16, A_WLD);
#pragma unroll
                    for (int i = 0; i < 4; i++)
#pragma unroll
                        for (int jj = 0; jj < 2; jj++)
                            wmma::mma_sync(acc[i][jj], af[i], bf[jj], acc[i][jj]);
                }
            }
        }
    }
    __syncthreads();

    // ---- LN2 epilogue: residual from x1 (smem), write Xh (+X on last) ----
    float4 gv = *(const float4*)(g2  + lane * 4);
    float4 bv = *(const float4*)(be2 + lane * 4);
    float4 bz = *(const float4*)(b2  + lane * 4);
#pragma unroll
    for (int pass = 0; pass < 2; pass++) {
        if (wm2 == pass) {
#pragma unroll
            for (int i = 0; i < 4; i++)
#pragma unroll
                for (int jj = 0; jj < 2; jj++)
                    wmma::store_matrix_sync(stg + (i * 16) * 132 + wn2 * 32 + jj * 16,
                                            acc[i][jj], 132, wmma::mem_row_major);
        }
        __syncthreads();
#pragma unroll
        for (int rr = 0; rr < 8; rr++) {
            const int r64 = wid * 8 + rr;
            const int rloc = pass * 64 + r64;
            float4 v = *(float4*)(stg + r64 * 132 + lane * 4);
            const size_t off = (bm + rloc) * DD + lane * 4;
            uint2 ru = *(const uint2*)(x1 + rloc * A_LD + lane * 4);
            float2 x0 = __half22float2(*(const __half2*)&ru.x);
            float2 xx1 = __half22float2(*(const __half2*)&ru.y);
            float4 tv;
            tv.x = v.x + bz.x + x0.x; tv.y = v.y + bz.y + x0.y;
            tv.z = v.z + bz.z + xx1.x; tv.w = v.w + bz.w + xx1.y;
            float s  = tv.x + tv.y + tv.z + tv.w;
            float s2 = tv.x*tv.x + tv.y*tv.y + tv.z*tv.z + tv.w*tv.w;
#pragma unroll
            for (int o = 16; o > 0; o >>= 1) {
                s  += __shfl_xor_sync(0xffffffffu, s,  o);
                s2 += __shfl_xor_sync(0xffffffffu, s2, o);
            }
            float mean = s * (1.f / DD);
            float var  = s2 * (1.f / DD) - mean * mean;
            float rstd = rsqrtf(var + 1e-5f);
            float4 y;
            y.x = (tv.x - mean) * rstd * gv.x + bv.x;
            y.y = (tv.y - mean) * rstd * gv.y + bv.y;
            y.z = (tv.z - mean) * rstd * gv.z + bv.z;
            y.w = (tv.w - mean) * rstd * gv.w + bv.w;
            if (wx) *(float4*)(X + off) = y;
            __half2 h0 = __floats2half2_rn(y.x, y.y);
            __half2 h1 = __floats2half2_rn(y.z, y.w);
            uint2 u;
            u.x = *reinterpret_cast<uint32_t*>(&h0);
            u.y = *reinterpret_cast<uint32_t*>(&h1);
            *(uint2*)(Xh + off) = u;
        }
        __syncthreads();
    }
}

// ---------------------------------------------------------------------------
extern "C" void kernel_launch(void* const* d_in, const int* in_sizes, int n_in,
                              void* d_out, int out_size)
{
    const float* x_in      = (const float*)d_in[0];
    const float* mask      = (const float*)d_in[1];
    const float* in_proj_w = (const float*)d_in[2];
    const float* in_proj_b = (const float*)d_in[3];
    const float* out_w     = (const float*)d_in[4];
    const float* out_b     = (const float*)d_in[5];
    const float* ln1_g     = (const float*)d_in[6];
    const float* ln1_b     = (const float*)d_in[7];
    const float* ff1_w     = (const float*)d_in[8];
    const float* ff1_b     = (const float*)d_in[9];
    const float* ff2_w     = (const float*)d_in[10];
    const float* ff2_b     = (const float*)d_in[11];
    const float* ln2_g     = (const float*)d_in[12];
    const float* ln2_b     = (const float*)d_in[13];
    float* x = (float*)d_out;

    __half *wqkv, *wout, *wff1, *wff2, *xh, *qkvh, *attnh;
    cudaGetSymbolAddress((void**)&wqkv, g_wqkv);
    cudaGetSymbolAddress((void**)&wout, g_wout);
    cudaGetSymbolAddress((void**)&wff1, g_wff1);
    cudaGetSymbolAddress((void**)&wff2, g_wff2);
    cudaGetSymbolAddress((void**)&xh,   g_xh);
    cudaGetSymbolAddress((void**)&qkvh, g_qkvh);
    cudaGetSymbolAddress((void**)&attnh,g_attnh);

    cudaFuncSetAttribute(gemm_h,   cudaFuncAttributeMaxDynamicSharedMemorySize, SMEM_DYN);
    cudaFuncSetAttribute(attn_tc,  cudaFuncAttributeMaxDynamicSharedMemorySize, ATT_SMEM);
    cudaFuncSetAttribute(of_fused, cudaFuncAttributeMaxDynamicSharedMemorySize, F_SMEM);

    cvt_all<<<(N_CVT + 255) / 256, 256>>>(x_in, in_proj_w, out_w, ff1_w, ff2_w);

    for (int l = 0; l < NL; l++) {
        gemm_h<<<dim3(3, MM / 128), 256, SMEM_DYN>>>(
            xh, wqkv + (size_t)l * 3 * DD * DD, in_proj_b + (size_t)l * 3 * DD,
            qkvh, 3 * DD, DD);
        attn_tc<<<BB * HH, 256, ATT_SMEM>>>(qkvh, mask, attnh);
        of_fused<<<MM / 128, 256, F_SMEM>>>(
            attnh, wout + (size_t)l * DD * DD, out_b + (size_t)l * DD,
            ln1_g + (size_t)l * DD, ln1_b + (size_t)l * DD,
            wff1 + (size_t)l * FFD * DD, ff1_b + (size_t)l * FFD,
            wff2 + (size_t)l * DD * FFD, ff2_b + (size_t)l * DD,
            ln2_g + (size_t)l * DD, ln2_b + (size_t)l * DD,
            xh, x, (l == NL - 1) ? 1 : 0);
    }
}